// round 5
// baseline (speedup 1.0000x reference)
#include <cuda_runtime.h>
#include <cuda_bf16.h>
#include <math.h>

// ---------------------------------------------------------------------------
// Problem constants
// ---------------------------------------------------------------------------
#define BATCH   8
#define SEQ     1024
#define EMBED   768
#define HEADS   12
#define HD      64
#define HIDDEN  3072
#define MTOK    (BATCH * SEQ)          // 8192 tokens
#define QKVC    (3 * EMBED)            // 2304

// ---------------------------------------------------------------------------
// Scratch buffers (static __device__ arrays: allocation-free per harness rules)
// ---------------------------------------------------------------------------
__device__ __align__(16) float g_ln [MTOK * EMBED];    // LN output (ln1 & ln2)
__device__ __align__(16) float g_qkv[MTOK * QKVC];     // fused QKV output
__device__ __align__(16) float g_ctx[MTOK * EMBED];    // attn ctx, [b, n, h, hd]
__device__ __align__(16) float g_x1 [MTOK * EMBED];    // after attention residual
__device__ __align__(16) float g_fc1[MTOK * HIDDEN];   // gelu(fc1) output

// ---------------------------------------------------------------------------
// LayerNorm: one block per row (768 elems), 256 threads, 3 elems/thread
// ---------------------------------------------------------------------------
__global__ __launch_bounds__(256) void ln_kernel(
    const float* __restrict__ x, const float* __restrict__ g,
    const float* __restrict__ bvec, float* __restrict__ out)
{
    int row = blockIdx.x;
    const float* xr = x + (size_t)row * EMBED;
    float* orow = out + (size_t)row * EMBED;
    int t = threadIdx.x;

    float v0 = xr[t], v1 = xr[t + 256], v2 = xr[t + 512];
    float s  = v0 + v1 + v2;
    float ss = v0 * v0 + v1 * v1 + v2 * v2;

    __shared__ float red0[8], red1[8];
    int lane = t & 31, wid = t >> 5;
    #pragma unroll
    for (int o = 16; o; o >>= 1) {
        s  += __shfl_xor_sync(0xffffffffu, s,  o);
        ss += __shfl_xor_sync(0xffffffffu, ss, o);
    }
    if (lane == 0) { red0[wid] = s; red1[wid] = ss; }
    __syncthreads();
    if (t < 32) {
        s  = (t < 8) ? red0[t] : 0.f;
        ss = (t < 8) ? red1[t] : 0.f;
        #pragma unroll
        for (int o = 4; o; o >>= 1) {
            s  += __shfl_xor_sync(0xffffffffu, s,  o);
            ss += __shfl_xor_sync(0xffffffffu, ss, o);
        }
        if (t == 0) { red0[0] = s; red1[0] = ss; }
    }
    __syncthreads();
    float mean = red0[0] * (1.0f / EMBED);
    float var  = red1[0] * (1.0f / EMBED) - mean * mean;
    float rstd = rsqrtf(var + 1e-5f);

    orow[t]       = (v0 - mean) * rstd * g[t]       + bvec[t];
    orow[t + 256] = (v1 - mean) * rstd * g[t + 256] + bvec[t + 256];
    orow[t + 512] = (v2 - mean) * rstd * g[t + 512] + bvec[t + 512];
}

// ---------------------------------------------------------------------------
// SGEMM:  C[M,N] = A[M,K] @ W[N,K]^T + bias (+ epilogue)
// Both operands K-contiguous (NT). 128x128 tile, BK=8, 256 thr, 8x8 microtile.
// EPI: 0 = bias only, 1 = bias + residual add, 2 = bias + exact GELU
// ---------------------------------------------------------------------------
template<int EPI>
__global__ __launch_bounds__(256) void sgemm_kernel(
    const float* __restrict__ A, const float* __restrict__ W,
    const float* __restrict__ bias, const float* __restrict__ Res,
    float* __restrict__ C, int M, int Nc, int K)
{
    __shared__ __align__(16) float As[8][128];
    __shared__ __align__(16) float Bs[8][128];

    int bm = blockIdx.y * 128;
    int bn = blockIdx.x * 128;
    int tid = threadIdx.x;

    int lrow = tid >> 1;            // 0..127
    int lcol = (tid & 1) << 2;      // 0 or 4
    const float* Aptr = A + (size_t)(bm + lrow) * K + lcol;
    const float* Wptr = W + (size_t)(bn + lrow) * K + lcol;

    int ty = tid >> 4, tx = tid & 15;
    float acc[8][8];
    #pragma unroll
    for (int i = 0; i < 8; ++i)
        #pragma unroll
        for (int j = 0; j < 8; ++j) acc[i][j] = 0.f;

    for (int kk = 0; kk < K; kk += 8) {
        float4 a4 = *(const float4*)(Aptr + kk);
        float4 b4 = *(const float4*)(Wptr + kk);
        __syncthreads();
        As[lcol + 0][lrow] = a4.x; As[lcol + 1][lrow] = a4.y;
        As[lcol + 2][lrow] = a4.z; As[lcol + 3][lrow] = a4.w;
        Bs[lcol + 0][lrow] = b4.x; Bs[lcol + 1][lrow] = b4.y;
        Bs[lcol + 2][lrow] = b4.z; Bs[lcol + 3][lrow] = b4.w;
        __syncthreads();
        #pragma unroll
        for (int k = 0; k < 8; ++k) {
            float av[8], bv[8];
            *(float4*)&av[0] = *(const float4*)&As[k][ty * 8];
            *(float4*)&av[4] = *(const float4*)&As[k][ty * 8 + 4];
            *(float4*)&bv[0] = *(const float4*)&Bs[k][tx * 8];
            *(float4*)&bv[4] = *(const float4*)&Bs[k][tx * 8 + 4];
            #pragma unroll
            for (int i = 0; i < 8; ++i)
                #pragma unroll
                for (int j = 0; j < 8; ++j)
                    acc[i][j] += av[i] * bv[j];
        }
    }

    int crow0 = bm + ty * 8;
    int ccol  = bn + tx * 8;
    #pragma unroll
    for (int i = 0; i < 8; ++i) {
        size_t off = (size_t)(crow0 + i) * Nc + ccol;
        #pragma unroll
        for (int j = 0; j < 8; j += 4) {
            float cv[4];
            #pragma unroll
            for (int u = 0; u < 4; ++u) {
                float t = acc[i][j + u] + bias[ccol + j + u];
                if (EPI == 1) t += Res[off + j + u];
                if (EPI == 2) t = 0.5f * t * (1.0f + erff(t * 0.70710678118654752f));
                cv[u] = t;
            }
            *(float4*)&C[off + j] = make_float4(cv[0], cv[1], cv[2], cv[3]);
        }
    }
}

// ---------------------------------------------------------------------------
// Fused attention, thread-per-query (correct by construction).
// grid = (SEQ/128, BATCH*HEADS), block = 128 threads.
// Each thread owns ONE query row: Q[64] and acc[64] in registers; scalar
// online softmax; K/V stream through 16 KB static smem in 32-key tiles with
// float4 broadcast reads (all lanes read the same K/V element -> 1 phase).
// qkv row layout per token: [Q(768) | K(768) | V(768)], head h at h*64.
// Writes ctx in [b, n, h, hd] layout.
// ---------------------------------------------------------------------------
#define KTILE 32

__global__ __launch_bounds__(128) void attn_kernel(
    const float* __restrict__ qkv, float* __restrict__ ctx)
{
    __shared__ __align__(16) float Ks[KTILE * 64];
    __shared__ __align__(16) float Vs[KTILE * 64];

    int bh = blockIdx.y;
    int b  = bh / HEADS;
    int h  = bh % HEADS;
    int tid = threadIdx.x;
    int q  = blockIdx.x * 128 + tid;     // this thread's query index in [0,SEQ)
    int hq = h * HD;
    const float* base = qkv + (size_t)(b * SEQ) * QKVC;

    // Q row into registers, pre-scaled by 1/sqrt(64)
    float qr[64];
    {
        const float4* qp = (const float4*)(base + (size_t)q * QKVC + hq);
        #pragma unroll
        for (int i = 0; i < 16; ++i) {
            float4 v = qp[i];
            qr[4*i+0] = v.x * 0.125f;
            qr[4*i+1] = v.y * 0.125f;
            qr[4*i+2] = v.z * 0.125f;
            qr[4*i+3] = v.w * 0.125f;
        }
    }

    float m = -1e30f, l = 0.f;
    float acc[64];
    #pragma unroll
    for (int d = 0; d < 64; ++d) acc[d] = 0.f;

    for (int t = 0; t < SEQ / KTILE; ++t) {
        int k0 = t * KTILE;
        __syncthreads();   // previous tile fully consumed by all threads
        // cooperative K/V tile load: KTILE tokens x 64 dims, float4
        for (int i = tid; i < KTILE * 16; i += 128) {
            int r  = i >> 4;            // 0..KTILE-1
            int c4 = (i & 15) << 2;     // 0..60
            const float* trow = base + (size_t)(k0 + r) * QKVC + hq;
            *(float4*)&Ks[r * 64 + c4] = *(const float4*)(trow + EMBED + c4);
            *(float4*)&Vs[r * 64 + c4] = *(const float4*)(trow + 2 * EMBED + c4);
        }
        __syncthreads();

        for (int k = 0; k < KTILE; ++k) {
            // score = q . k  (4 partial chains for ILP)
            float s0 = 0.f, s1 = 0.f, s2 = 0.f, s3 = 0.f;
            #pragma unroll
            for (int d4 = 0; d4 < 16; ++d4) {
                float4 kv = *(const float4*)&Ks[k * 64 + d4 * 4];
                s0 += qr[d4*4+0] * kv.x;
                s1 += qr[d4*4+1] * kv.y;
                s2 += qr[d4*4+2] * kv.z;
                s3 += qr[d4*4+3] * kv.w;
            }
            float s = (s0 + s1) + (s2 + s3);

            if (s > m) {                       // rescale path (rare after warmup)
                float corr = __expf(m - s);
                l *= corr;
                #pragma unroll
                for (int d = 0; d < 64; ++d) acc[d] *= corr;
                m = s;
            }
            float p = __expf(s - m);
            l += p;
            #pragma unroll
            for (int d4 = 0; d4 < 16; ++d4) {
                float4 vv = *(const float4*)&Vs[k * 64 + d4 * 4];
                acc[d4*4+0] += p * vv.x;
                acc[d4*4+1] += p * vv.y;
                acc[d4*4+2] += p * vv.z;
                acc[d4*4+3] += p * vv.w;
            }
        }
    }

    // finalize: ctx[b, q, h, d] = acc / l
    float inv = 1.0f / l;
    float* orow = ctx + ((size_t)(b * SEQ) + q) * EMBED + hq;
    #pragma unroll
    for (int d4 = 0; d4 < 16; ++d4) {
        float4 o;
        o.x = acc[d4*4+0] * inv;
        o.y = acc[d4*4+1] * inv;
        o.z = acc[d4*4+2] * inv;
        o.w = acc[d4*4+3] * inv;
        *(float4*)&orow[d4 * 4] = o;
    }
}

// ---------------------------------------------------------------------------
// Launch
// ---------------------------------------------------------------------------
extern "C" void kernel_launch(void* const* d_in, const int* in_sizes, int n_in,
                              void* d_out, int out_size)
{
    const float* x      = (const float*)d_in[0];
    const float* ln1_g  = (const float*)d_in[1];
    const float* ln1_b  = (const float*)d_in[2];
    const float* qkv_w  = (const float*)d_in[3];
    const float* qkv_b  = (const float*)d_in[4];
    const float* proj_w = (const float*)d_in[5];
    const float* proj_b = (const float*)d_in[6];
    const float* ln2_g  = (const float*)d_in[7];
    const float* ln2_b  = (const float*)d_in[8];
    const float* fc1_w  = (const float*)d_in[9];
    const float* fc1_b  = (const float*)d_in[10];
    const float* fc2_w  = (const float*)d_in[11];
    const float* fc2_b  = (const float*)d_in[12];
    float* out = (float*)d_out;

    float *p_ln, *p_qkv, *p_ctx, *p_x1, *p_fc1;
    cudaGetSymbolAddress((void**)&p_ln,  g_ln);
    cudaGetSymbolAddress((void**)&p_qkv, g_qkv);
    cudaGetSymbolAddress((void**)&p_ctx, g_ctx);
    cudaGetSymbolAddress((void**)&p_x1,  g_x1);
    cudaGetSymbolAddress((void**)&p_fc1, g_fc1);

    // 1) LN1
    ln_kernel<<<MTOK, 256>>>(x, ln1_g, ln1_b, p_ln);
    // 2) QKV GEMM: [8192,768] @ [2304,768]^T
    sgemm_kernel<0><<<dim3(QKVC / 128, MTOK / 128), 256>>>(
        p_ln, qkv_w, qkv_b, nullptr, p_qkv, MTOK, QKVC, EMBED);
    // 3) attention (thread-per-query, static smem, no opt-in needed)
    attn_kernel<<<dim3(SEQ / 128, BATCH * HEADS), 128>>>(p_qkv, p_ctx);
    // 4) proj GEMM + residual:  x1 = x + ctx @ proj_w^T + proj_b
    sgemm_kernel<1><<<dim3(EMBED / 128, MTOK / 128), 256>>>(
        p_ctx, proj_w, proj_b, x, p_x1, MTOK, EMBED, EMBED);
    // 5) LN2
    ln_kernel<<<MTOK, 256>>>(p_x1, ln2_g, ln2_b, p_ln);
    // 6) FC1 GEMM + exact GELU
    sgemm_kernel<2><<<dim3(HIDDEN / 128, MTOK / 128), 256>>>(
        p_ln, fc1_w, fc1_b, nullptr, p_fc1, MTOK, HIDDEN, EMBED);
    // 7) FC2 GEMM + residual -> final output
    sgemm_kernel<1><<<dim3(EMBED / 128, MTOK / 128), 256>>>(
        p_fc1, fc2_w, fc2_b, p_x1, out, MTOK, EMBED, HIDDEN);
}

// round 7
// speedup vs baseline: 1.3455x; 1.3455x over previous
#include <cuda_runtime.h>
#include <cuda_bf16.h>
#include <mma.h>
#include <math.h>
#include <stdint.h>

using namespace nvcuda;

// ---------------------------------------------------------------------------
// Problem constants
// ---------------------------------------------------------------------------
#define BATCH   8
#define SEQ     1024
#define EMBED   768
#define HEADS   12
#define HD      64
#define HIDDEN  3072
#define MTOK    (BATCH * SEQ)          // 8192 tokens
#define QKVC    (3 * EMBED)            // 2304
#define KP1     (3 * EMBED)            // 2304 = split-K' for K=768
#define KP2     (3 * HIDDEN)           // 9216 = split-K' for K=3072

// ---------------------------------------------------------------------------
// Scratch (static __device__: allocation-free per harness rules)
// Split-bf16 along K':  A-form = [hi | lo | hi],  B-form = [hi | hi | lo]
// => K'-concatenated bf16 GEMM computes ah*bh + al*bh + ah*bl (≈fp32 accurate)
// ---------------------------------------------------------------------------
__device__ __align__(16) float         g_qkv [(size_t)MTOK * QKVC];
__device__ __align__(16) float         g_x1  [(size_t)MTOK * EMBED];
__device__ __align__(16) __nv_bfloat16 g_as  [(size_t)MTOK * KP1];
__device__ __align__(16) __nv_bfloat16 g_ctxs[(size_t)MTOK * KP1];
__device__ __align__(16) __nv_bfloat16 g_f1s [(size_t)MTOK * KP2];
__device__ __align__(16) __nv_bfloat16 g_wq  [(size_t)QKVC  * KP1];
__device__ __align__(16) __nv_bfloat16 g_wp  [(size_t)EMBED * KP1];
__device__ __align__(16) __nv_bfloat16 g_w1  [(size_t)HIDDEN* KP1];
__device__ __align__(16) __nv_bfloat16 g_w2  [(size_t)EMBED * KP2];

__device__ __forceinline__ void split2(float v0, float v1, __nv_bfloat162& hi, __nv_bfloat162& lo) {
    __nv_bfloat16 h0 = __float2bfloat16(v0), h1 = __float2bfloat16(v1);
    hi.x = h0; hi.y = h1;
    lo.x = __float2bfloat16(v0 - __bfloat162float(h0));
    lo.y = __float2bfloat16(v1 - __bfloat162float(h1));
}

// ---------------------------------------------------------------------------
// Weight split: W[rows,K] fp32 -> out[rows,3K] bf16 B-form [hi|hi|lo]
// ---------------------------------------------------------------------------
__global__ void wsplit_kernel(const float* __restrict__ W, __nv_bfloat16* __restrict__ out,
                              int rows, int K)
{
    int total = rows * (K >> 1);
    for (int i = blockIdx.x * blockDim.x + threadIdx.x; i < total; i += gridDim.x * blockDim.x) {
        int e = i << 1;
        int r = e / K, k = e - r * K;
        float2 v = *(const float2*)&W[(size_t)r * K + k];
        __nv_bfloat162 hi, lo;
        split2(v.x, v.y, hi, lo);
        __nv_bfloat16* o = out + (size_t)r * 3 * K + k;
        *(__nv_bfloat162*)(o)         = hi;
        *(__nv_bfloat162*)(o + K)     = hi;
        *(__nv_bfloat162*)(o + 2 * K) = lo;
    }
}

// ---------------------------------------------------------------------------
// LayerNorm -> split-A bf16 [hi|lo|hi] (row length 2304)
// ---------------------------------------------------------------------------
__global__ __launch_bounds__(256) void ln_kernel(
    const float* __restrict__ x, const float* __restrict__ g,
    const float* __restrict__ bvec, __nv_bfloat16* __restrict__ out)
{
    int row = blockIdx.x;
    const float* xr = x + (size_t)row * EMBED;
    int t = threadIdx.x;

    float v0 = xr[t], v1 = xr[t + 256], v2 = xr[t + 512];
    float s  = v0 + v1 + v2;
    float ss = v0 * v0 + v1 * v1 + v2 * v2;

    __shared__ float red0[8], red1[8];
    int lane = t & 31, wid = t >> 5;
    #pragma unroll
    for (int o = 16; o; o >>= 1) {
        s  += __shfl_xor_sync(0xffffffffu, s,  o);
        ss += __shfl_xor_sync(0xffffffffu, ss, o);
    }
    if (lane == 0) { red0[wid] = s; red1[wid] = ss; }
    __syncthreads();
    if (t < 32) {
        s  = (t < 8) ? red0[t] : 0.f;
        ss = (t < 8) ? red1[t] : 0.f;
        #pragma unroll
        for (int o = 4; o; o >>= 1) {
            s  += __shfl_xor_sync(0xffffffffu, s,  o);
            ss += __shfl_xor_sync(0xffffffffu, ss, o);
        }
        if (t == 0) { red0[0] = s; red1[0] = ss; }
    }
    __syncthreads();
    float mean = red0[0] * (1.0f / EMBED);
    float var  = red1[0] * (1.0f / EMBED) - mean * mean;
    float rstd = rsqrtf(var + 1e-5f);

    __nv_bfloat16* orow = out + (size_t)row * KP1;
    #pragma unroll
    for (int u = 0; u < 3; ++u) {
        int i = t + u * 256;
        float v = (u == 0 ? v0 : (u == 1 ? v1 : v2));
        float y = (v - mean) * rstd * g[i] + bvec[i];
        __nv_bfloat16 h = __float2bfloat16(y);
        __nv_bfloat16 l = __float2bfloat16(y - __bfloat162float(h));
        orow[i]        = h;
        orow[768 + i]  = l;
        orow[1536 + i] = h;
    }
}

// ---------------------------------------------------------------------------
// WMMA bf16 GEMM: C[M,N] = A'[M,K'] * B'[N,K']^T (+bias, epilogue)
// 128x128 tile, 256 thr (8 warps 4x2), warp 32x64 = 2x4 wmma 16x16x16 frags.
// Double-buffered smem, 40-elem padded rows (LDSM conflict-free).
// EPI: 0 = bias -> fp32 C; 1 = bias+Res -> fp32 C; 2 = bias+GELU -> split bf16 Cs
// ---------------------------------------------------------------------------
#define LDS 40

template<int EPI>
__global__ __launch_bounds__(256) void tc_gemm(
    const __nv_bfloat16* __restrict__ A, const __nv_bfloat16* __restrict__ B,
    const float* __restrict__ bias, const float* __restrict__ Res,
    float* __restrict__ C, __nv_bfloat16* __restrict__ Cs,
    int N, int Kp)
{
    __shared__ __align__(16) __nv_bfloat16 As[2][128 * LDS];
    __shared__ __align__(16) __nv_bfloat16 Bs[2][128 * LDS];

    int tid  = threadIdx.x;
    int warp = tid >> 5, lane = tid & 31;
    int wm = warp >> 1, wn = warp & 1;
    int bm = blockIdx.y * 128, bn = blockIdx.x * 128;

    // global-load coords: each thread loads 2 float4 (rows tid/4 and tid/4+64)
    int grow = tid >> 2;
    int gcol = (tid & 3) << 3;
    const __nv_bfloat16* Ag = A + (size_t)(bm + grow) * Kp + gcol;
    const __nv_bfloat16* Bg = B + (size_t)(bn + grow) * Kp + gcol;
    const size_t half = (size_t)64 * Kp;

    wmma::fragment<wmma::accumulator, 16, 16, 16, float> acc[2][4];
    #pragma unroll
    for (int i = 0; i < 2; ++i)
        #pragma unroll
        for (int j = 0; j < 4; ++j) wmma::fill_fragment(acc[i][j], 0.0f);

    int nk = Kp >> 5;   // K'-chunks of 32
    float4 ra0, ra1, rb0, rb1;

    // prologue: load chunk 0
    ra0 = *(const float4*)(Ag);        ra1 = *(const float4*)(Ag + half);
    rb0 = *(const float4*)(Bg);        rb1 = *(const float4*)(Bg + half);

    for (int t = 0; t < nk; ++t) {
        int st = t & 1;
        // stage regs -> smem
        *(float4*)&As[st][grow * LDS + gcol]        = ra0;
        *(float4*)&As[st][(grow + 64) * LDS + gcol] = ra1;
        *(float4*)&Bs[st][grow * LDS + gcol]        = rb0;
        *(float4*)&Bs[st][(grow + 64) * LDS + gcol] = rb1;
        __syncthreads();

        // prefetch next chunk
        if (t + 1 < nk) {
            const __nv_bfloat16* An = Ag + ((t + 1) << 5);
            const __nv_bfloat16* Bn = Bg + ((t + 1) << 5);
            ra0 = *(const float4*)(An);      ra1 = *(const float4*)(An + half);
            rb0 = *(const float4*)(Bn);      rb1 = *(const float4*)(Bn + half);
        }

        // compute on current buffer
        #pragma unroll
        for (int ks = 0; ks < 2; ++ks) {
            wmma::fragment<wmma::matrix_a, 16, 16, 16, __nv_bfloat16, wmma::row_major> af[2];
            wmma::fragment<wmma::matrix_b, 16, 16, 16, __nv_bfloat16, wmma::col_major> bf[4];
            #pragma unroll
            for (int i = 0; i < 2; ++i)
                wmma::load_matrix_sync(af[i], &As[st][(wm * 32 + i * 16) * LDS + ks * 16], LDS);
            #pragma unroll
            for (int j = 0; j < 4; ++j)
                wmma::load_matrix_sync(bf[j], &Bs[st][(wn * 64 + j * 16) * LDS + ks * 16], LDS);
            #pragma unroll
            for (int i = 0; i < 2; ++i)
                #pragma unroll
                for (int j = 0; j < 4; ++j)
                    wmma::mma_sync(acc[i][j], af[i], bf[j], acc[i][j]);
        }
        __syncthreads();
    }

    // ---- epilogue: stage each frag through smem (reuse As), vector write ----
    float* stage = reinterpret_cast<float*>(&As[0][0]);
    float* ws = stage + warp * 256;
    int er = lane >> 1, ec = (lane & 1) << 3;   // each lane: 8 elems of one row

    #pragma unroll
    for (int i = 0; i < 2; ++i) {
        #pragma unroll
        for (int j = 0; j < 4; ++j) {
            wmma::store_matrix_sync(ws, acc[i][j], 16, wmma::mem_row_major);
            __syncwarp();
            int row = bm + wm * 32 + i * 16 + er;
            int col = bn + wn * 64 + j * 16 + ec;
            float v[8];
            #pragma unroll
            for (int u = 0; u < 8; ++u) v[u] = ws[er * 16 + ec + u] + bias[col + u];
            if (EPI == 2) {
                size_t rb = (size_t)row * (3 * (size_t)N);
                #pragma unroll
                for (int u = 0; u < 8; u += 2) {
                    float g0 = 0.5f * v[u]     * (1.0f + erff(v[u]     * 0.70710678118654752f));
                    float g1 = 0.5f * v[u + 1] * (1.0f + erff(v[u + 1] * 0.70710678118654752f));
                    __nv_bfloat162 hi, lo;
                    split2(g0, g1, hi, lo);
                    *(__nv_bfloat162*)&Cs[rb + col + u]         = hi;
                    *(__nv_bfloat162*)&Cs[rb + N + col + u]     = lo;
                    *(__nv_bfloat162*)&Cs[rb + 2 * N + col + u] = hi;
                }
            } else {
                size_t off = (size_t)row * N + col;
                if (EPI == 1) {
                    float4 r0 = *(const float4*)&Res[off];
                    float4 r1 = *(const float4*)&Res[off + 4];
                    v[0] += r0.x; v[1] += r0.y; v[2] += r0.z; v[3] += r0.w;
                    v[4] += r1.x; v[5] += r1.y; v[6] += r1.z; v[7] += r1.w;
                }
                *(float4*)&C[off]     = make_float4(v[0], v[1], v[2], v[3]);
                *(float4*)&C[off + 4] = make_float4(v[4], v[5], v[6], v[7]);
            }
            __syncwarp();
        }
    }
}

// ---------------------------------------------------------------------------
// Fused attention, thread-per-query (validated R5). Writes split-A bf16 ctx.
// ---------------------------------------------------------------------------
#define KTILE 32

__global__ __launch_bounds__(128) void attn_kernel(
    const float* __restrict__ qkv, __nv_bfloat16* __restrict__ ctxs)
{
    __shared__ __align__(16) float Ks[KTILE * 64];
    __shared__ __align__(16) float Vs[KTILE * 64];

    int bh = blockIdx.y;
    int b  = bh / HEADS;
    int h  = bh % HEADS;
    int tid = threadIdx.x;
    int q  = blockIdx.x * 128 + tid;
    int hq = h * HD;
    const float* base = qkv + (size_t)(b * SEQ) * QKVC;

    float qr[64];
    {
        const float4* qp = (const float4*)(base + (size_t)q * QKVC + hq);
        #pragma unroll
        for (int i = 0; i < 16; ++i) {
            float4 v = qp[i];
            qr[4*i+0] = v.x * 0.125f;
            qr[4*i+1] = v.y * 0.125f;
            qr[4*i+2] = v.z * 0.125f;
            qr[4*i+3] = v.w * 0.125f;
        }
    }

    float m = -1e30f, l = 0.f;
    float acc[64];
    #pragma unroll
    for (int d = 0; d < 64; ++d) acc[d] = 0.f;

    for (int t = 0; t < SEQ / KTILE; ++t) {
        int k0 = t * KTILE;
        __syncthreads();
        for (int i = tid; i < KTILE * 16; i += 128) {
            int r  = i >> 4;
            int c4 = (i & 15) << 2;
            const float* trow = base + (size_t)(k0 + r) * QKVC + hq;
            *(float4*)&Ks[r * 64 + c4] = *(const float4*)(trow + EMBED + c4);
            *(float4*)&Vs[r * 64 + c4] = *(const float4*)(trow + 2 * EMBED + c4);
        }
        __syncthreads();

        for (int k = 0; k < KTILE; ++k) {
            float s0 = 0.f, s1 = 0.f, s2 = 0.f, s3 = 0.f;
            #pragma unroll
            for (int d4 = 0; d4 < 16; ++d4) {
                float4 kv = *(const float4*)&Ks[k * 64 + d4 * 4];
                s0 += qr[d4*4+0] * kv.x;
                s1 += qr[d4*4+1] * kv.y;
                s2 += qr[d4*4+2] * kv.z;
                s3 += qr[d4*4+3] * kv.w;
            }
            float s = (s0 + s1) + (s2 + s3);

            if (s > m) {
                float corr = __expf(m - s);
                l *= corr;
                #pragma unroll
                for (int d = 0; d < 64; ++d) acc[d] *= corr;
                m = s;
            }
            float p = __expf(s - m);
            l += p;
            #pragma unroll
            for (int d4 = 0; d4 < 16; ++d4) {
                float4 vv = *(const float4*)&Vs[k * 64 + d4 * 4];
                acc[d4*4+0] += p * vv.x;
                acc[d4*4+1] += p * vv.y;
                acc[d4*4+2] += p * vv.z;
                acc[d4*4+3] += p * vv.w;
            }
        }
    }

    float inv = 1.0f / l;
    size_t rb = ((size_t)(b * SEQ) + q) * KP1;
    #pragma unroll
    for (int d = 0; d < 64; d += 2) {
        __nv_bfloat162 hi, lo;
        split2(acc[d] * inv, acc[d + 1] * inv, hi, lo);
        *(__nv_bfloat162*)&ctxs[rb + hq + d]        = hi;
        *(__nv_bfloat162*)&ctxs[rb + 768 + hq + d]  = lo;
        *(__nv_bfloat162*)&ctxs[rb + 1536 + hq + d] = hi;
    }
}

// ---------------------------------------------------------------------------
// Launch
// ---------------------------------------------------------------------------
extern "C" void kernel_launch(void* const* d_in, const int* in_sizes, int n_in,
                              void* d_out, int out_size)
{
    const float* x      = (const float*)d_in[0];
    const float* ln1_g  = (const float*)d_in[1];
    const float* ln1_b  = (const float*)d_in[2];
    const float* qkv_w  = (const float*)d_in[3];
    const float* qkv_b  = (const float*)d_in[4];
    const float* proj_w = (const float*)d_in[5];
    const float* proj_b = (const float*)d_in[6];
    const float* ln2_g  = (const float*)d_in[7];
    const float* ln2_b  = (const float*)d_in[8];
    const float* fc1_w  = (const float*)d_in[9];
    const float* fc1_b  = (const float*)d_in[10];
    const float* fc2_w  = (const float*)d_in[11];
    const float* fc2_b  = (const float*)d_in[12];
    float* out = (float*)d_out;

    float *p_qkv, *p_x1;
    __nv_bfloat16 *p_as, *p_ctxs, *p_f1s, *p_wq, *p_wp, *p_w1, *p_w2;
    cudaGetSymbolAddress((void**)&p_qkv,  g_qkv);
    cudaGetSymbolAddress((void**)&p_x1,   g_x1);
    cudaGetSymbolAddress((void**)&p_as,   g_as);
    cudaGetSymbolAddress((void**)&p_ctxs, g_ctxs);
    cudaGetSymbolAddress((void**)&p_f1s,  g_f1s);
    cudaGetSymbolAddress((void**)&p_wq,   g_wq);
    cudaGetSymbolAddress((void**)&p_wp,   g_wp);
    cudaGetSymbolAddress((void**)&p_w1,   g_w1);
    cudaGetSymbolAddress((void**)&p_w2,   g_w2);

    // weight splits (graph-replayed, deterministic)
    wsplit_kernel<<<1024, 256>>>(qkv_w,  p_wq, QKVC,  EMBED);
    wsplit_kernel<<<1024, 256>>>(proj_w, p_wp, EMBED, EMBED);
    wsplit_kernel<<<1024, 256>>>(fc1_w,  p_w1, HIDDEN, EMBED);
    wsplit_kernel<<<1024, 256>>>(fc2_w,  p_w2, EMBED, HIDDEN);

    // 1) LN1 -> split-A
    ln_kernel<<<MTOK, 256>>>(x, ln1_g, ln1_b, p_as);
    // 2) QKV GEMM (tensor) -> fp32 qkv
    tc_gemm<0><<<dim3(QKVC / 128, MTOK / 128), 256>>>(
        p_as, p_wq, qkv_b, nullptr, p_qkv, nullptr, QKVC, KP1);
    // 3) attention -> split-A ctx
    attn_kernel<<<dim3(SEQ / 128, BATCH * HEADS), 128>>>(p_qkv, p_ctxs);
    // 4) proj GEMM + residual -> fp32 x1
    tc_gemm<1><<<dim3(EMBED / 128, MTOK / 128), 256>>>(
        p_ctxs, p_wp, proj_b, x, p_x1, nullptr, EMBED, KP1);
    // 5) LN2 -> split-A
    ln_kernel<<<MTOK, 256>>>(p_x1, ln2_g, ln2_b, p_as);
    // 6) FC1 GEMM + GELU -> split-A bf16
    tc_gemm<2><<<dim3(HIDDEN / 128, MTOK / 128), 256>>>(
        p_as, p_w1, fc1_b, nullptr, nullptr, p_f1s, HIDDEN, KP1);
    // 7) FC2 GEMM + residual -> final fp32 output
    tc_gemm<1><<<dim3(EMBED / 128, MTOK / 128), 256>>>(
        p_f1s, p_w2, fc2_b, p_x1, out, nullptr, EMBED, KP2);
}

// round 8
// speedup vs baseline: 2.4016x; 1.7849x over previous
#include <cuda_runtime.h>
#include <cuda_bf16.h>
#include <mma.h>
#include <math.h>
#include <stdint.h>

using namespace nvcuda;

// ---------------------------------------------------------------------------
// Problem constants
// ---------------------------------------------------------------------------
#define BATCH   8
#define SEQ     1024
#define EMBED   768
#define HEADS   12
#define HD      64
#define HIDDEN  3072
#define MTOK    (BATCH * SEQ)          // 8192 tokens
#define QKVC    (3 * EMBED)            // 2304

// ---------------------------------------------------------------------------
// Scratch (static __device__: allocation-free per harness rules)
// Plain bf16 operands everywhere (fp32 accumulate). Precision budget analysis:
// expected final rel_err ~4e-4 << 1e-3 threshold.
// ---------------------------------------------------------------------------
__device__ __align__(16) float         g_qkv [(size_t)MTOK * QKVC];
__device__ __align__(16) float         g_x1  [(size_t)MTOK * EMBED];
__device__ __align__(16) __nv_bfloat16 g_as  [(size_t)MTOK * EMBED];    // LN out (reused)
__device__ __align__(16) __nv_bfloat16 g_ctxs[(size_t)MTOK * EMBED];    // attn ctx
__device__ __align__(16) __nv_bfloat16 g_f1s [(size_t)MTOK * HIDDEN];   // gelu(fc1)
__device__ __align__(16) __nv_bfloat16 g_wq  [(size_t)QKVC  * EMBED];
__device__ __align__(16) __nv_bfloat16 g_wp  [(size_t)EMBED * EMBED];
__device__ __align__(16) __nv_bfloat16 g_w1  [(size_t)HIDDEN* EMBED];
__device__ __align__(16) __nv_bfloat16 g_w2  [(size_t)EMBED * HIDDEN];

// ---------------------------------------------------------------------------
// Weight convert: W[rows,K] fp32 -> bf16
// ---------------------------------------------------------------------------
__global__ void wconv_kernel(const float* __restrict__ W, __nv_bfloat16* __restrict__ out,
                             size_t total)
{
    size_t i = ((size_t)blockIdx.x * blockDim.x + threadIdx.x) * 4;
    size_t stride = (size_t)gridDim.x * blockDim.x * 4;
    for (; i < total; i += stride) {
        float4 v = *(const float4*)&W[i];
        __nv_bfloat162 p0, p1;
        p0.x = __float2bfloat16(v.x); p0.y = __float2bfloat16(v.y);
        p1.x = __float2bfloat16(v.z); p1.y = __float2bfloat16(v.w);
        *(__nv_bfloat162*)&out[i]     = p0;
        *(__nv_bfloat162*)&out[i + 2] = p1;
    }
}

// ---------------------------------------------------------------------------
// LayerNorm -> bf16 row (768)
// ---------------------------------------------------------------------------
__global__ __launch_bounds__(256) void ln_kernel(
    const float* __restrict__ x, const float* __restrict__ g,
    const float* __restrict__ bvec, __nv_bfloat16* __restrict__ out)
{
    int row = blockIdx.x;
    const float* xr = x + (size_t)row * EMBED;
    int t = threadIdx.x;

    float v0 = xr[t], v1 = xr[t + 256], v2 = xr[t + 512];
    float s  = v0 + v1 + v2;
    float ss = v0 * v0 + v1 * v1 + v2 * v2;

    __shared__ float red0[8], red1[8];
    int lane = t & 31, wid = t >> 5;
    #pragma unroll
    for (int o = 16; o; o >>= 1) {
        s  += __shfl_xor_sync(0xffffffffu, s,  o);
        ss += __shfl_xor_sync(0xffffffffu, ss, o);
    }
    if (lane == 0) { red0[wid] = s; red1[wid] = ss; }
    __syncthreads();
    if (t < 32) {
        s  = (t < 8) ? red0[t] : 0.f;
        ss = (t < 8) ? red1[t] : 0.f;
        #pragma unroll
        for (int o = 4; o; o >>= 1) {
            s  += __shfl_xor_sync(0xffffffffu, s,  o);
            ss += __shfl_xor_sync(0xffffffffu, ss, o);
        }
        if (t == 0) { red0[0] = s; red1[0] = ss; }
    }
    __syncthreads();
    float mean = red0[0] * (1.0f / EMBED);
    float var  = red1[0] * (1.0f / EMBED) - mean * mean;
    float rstd = rsqrtf(var + 1e-5f);

    __nv_bfloat16* orow = out + (size_t)row * EMBED;
    orow[t]       = __float2bfloat16((v0 - mean) * rstd * g[t]       + bvec[t]);
    orow[t + 256] = __float2bfloat16((v1 - mean) * rstd * g[t + 256] + bvec[t + 256]);
    orow[t + 512] = __float2bfloat16((v2 - mean) * rstd * g[t + 512] + bvec[t + 512]);
}

// ---------------------------------------------------------------------------
// WMMA bf16 GEMM: C[M,N] = A[M,K] * B[N,K]^T (+bias, epilogue), fp32 accum
// 128x128 tile, 256 thr (8 warps 4x2), warp 32x64 = 2x4 wmma 16x16x16 frags.
// Double-buffered smem, 40-elem padded rows.
// EPI: 0 = bias -> fp32 C; 1 = bias+Res -> fp32 C; 2 = bias+GELU -> bf16 Cs
// ---------------------------------------------------------------------------
#define LDS 40

template<int EPI>
__global__ __launch_bounds__(256) void tc_gemm(
    const __nv_bfloat16* __restrict__ A, const __nv_bfloat16* __restrict__ B,
    const float* __restrict__ bias, const float* __restrict__ Res,
    float* __restrict__ C, __nv_bfloat16* __restrict__ Cs,
    int N, int Kp)
{
    __shared__ __align__(16) __nv_bfloat16 As[2][128 * LDS];
    __shared__ __align__(16) __nv_bfloat16 Bs[2][128 * LDS];

    int tid  = threadIdx.x;
    int warp = tid >> 5, lane = tid & 31;
    int wm = warp >> 1, wn = warp & 1;
    int bm = blockIdx.y * 128, bn = blockIdx.x * 128;

    int grow = tid >> 2;
    int gcol = (tid & 3) << 3;
    const __nv_bfloat16* Ag = A + (size_t)(bm + grow) * Kp + gcol;
    const __nv_bfloat16* Bg = B + (size_t)(bn + grow) * Kp + gcol;
    const size_t half = (size_t)64 * Kp;

    wmma::fragment<wmma::accumulator, 16, 16, 16, float> acc[2][4];
    #pragma unroll
    for (int i = 0; i < 2; ++i)
        #pragma unroll
        for (int j = 0; j < 4; ++j) wmma::fill_fragment(acc[i][j], 0.0f);

    int nk = Kp >> 5;
    float4 ra0, ra1, rb0, rb1;

    ra0 = *(const float4*)(Ag);        ra1 = *(const float4*)(Ag + half);
    rb0 = *(const float4*)(Bg);        rb1 = *(const float4*)(Bg + half);

    for (int t = 0; t < nk; ++t) {
        int st = t & 1;
        *(float4*)&As[st][grow * LDS + gcol]        = ra0;
        *(float4*)&As[st][(grow + 64) * LDS + gcol] = ra1;
        *(float4*)&Bs[st][grow * LDS + gcol]        = rb0;
        *(float4*)&Bs[st][(grow + 64) * LDS + gcol] = rb1;
        __syncthreads();

        if (t + 1 < nk) {
            const __nv_bfloat16* An = Ag + ((t + 1) << 5);
            const __nv_bfloat16* Bn = Bg + ((t + 1) << 5);
            ra0 = *(const float4*)(An);      ra1 = *(const float4*)(An + half);
            rb0 = *(const float4*)(Bn);      rb1 = *(const float4*)(Bn + half);
        }

        #pragma unroll
        for (int ks = 0; ks < 2; ++ks) {
            wmma::fragment<wmma::matrix_a, 16, 16, 16, __nv_bfloat16, wmma::row_major> af[2];
            wmma::fragment<wmma::matrix_b, 16, 16, 16, __nv_bfloat16, wmma::col_major> bf[4];
            #pragma unroll
            for (int i = 0; i < 2; ++i)
                wmma::load_matrix_sync(af[i], &As[st][(wm * 32 + i * 16) * LDS + ks * 16], LDS);
            #pragma unroll
            for (int j = 0; j < 4; ++j)
                wmma::load_matrix_sync(bf[j], &Bs[st][(wn * 64 + j * 16) * LDS + ks * 16], LDS);
            #pragma unroll
            for (int i = 0; i < 2; ++i)
                #pragma unroll
                for (int j = 0; j < 4; ++j)
                    wmma::mma_sync(acc[i][j], af[i], bf[j], acc[i][j]);
        }
        __syncthreads();
    }

    // ---- epilogue: stage each frag through smem (reuse As), vector write ----
    float* stage = reinterpret_cast<float*>(&As[0][0]);
    float* ws = stage + warp * 256;
    int er = lane >> 1, ec = (lane & 1) << 3;

    #pragma unroll
    for (int i = 0; i < 2; ++i) {
        #pragma unroll
        for (int j = 0; j < 4; ++j) {
            wmma::store_matrix_sync(ws, acc[i][j], 16, wmma::mem_row_major);
            __syncwarp();
            int row = bm + wm * 32 + i * 16 + er;
            int col = bn + wn * 64 + j * 16 + ec;
            float v[8];
            #pragma unroll
            for (int u = 0; u < 8; ++u) v[u] = ws[er * 16 + ec + u] + bias[col + u];
            if (EPI == 2) {
                size_t off = (size_t)row * N + col;
                #pragma unroll
                for (int u = 0; u < 8; u += 2) {
                    float g0 = 0.5f * v[u]     * (1.0f + erff(v[u]     * 0.70710678118654752f));
                    float g1 = 0.5f * v[u + 1] * (1.0f + erff(v[u + 1] * 0.70710678118654752f));
                    __nv_bfloat162 p;
                    p.x = __float2bfloat16(g0);
                    p.y = __float2bfloat16(g1);
                    *(__nv_bfloat162*)&Cs[off + u] = p;
                }
            } else {
                size_t off = (size_t)row * N + col;
                if (EPI == 1) {
                    float4 r0 = *(const float4*)&Res[off];
                    float4 r1 = *(const float4*)&Res[off + 4];
                    v[0] += r0.x; v[1] += r0.y; v[2] += r0.z; v[3] += r0.w;
                    v[4] += r1.x; v[5] += r1.y; v[6] += r1.z; v[7] += r1.w;
                }
                *(float4*)&C[off]     = make_float4(v[0], v[1], v[2], v[3]);
                *(float4*)&C[off + 4] = make_float4(v[4], v[5], v[6], v[7]);
            }
            __syncwarp();
        }
    }
}

// ---------------------------------------------------------------------------
// Fused attention, thread-per-query (validated R5). Writes bf16 ctx row (768).
// ---------------------------------------------------------------------------
#define KTILE 32

__global__ __launch_bounds__(128) void attn_kernel(
    const float* __restrict__ qkv, __nv_bfloat16* __restrict__ ctxs)
{
    __shared__ __align__(16) float Ks[KTILE * 64];
    __shared__ __align__(16) float Vs[KTILE * 64];

    int bh = blockIdx.y;
    int b  = bh / HEADS;
    int h  = bh % HEADS;
    int tid = threadIdx.x;
    int q  = blockIdx.x * 128 + tid;
    int hq = h * HD;
    const float* base = qkv + (size_t)(b * SEQ) * QKVC;

    float qr[64];
    {
        const float4* qp = (const float4*)(base + (size_t)q * QKVC + hq);
        #pragma unroll
        for (int i = 0; i < 16; ++i) {
            float4 v = qp[i];
            qr[4*i+0] = v.x * 0.125f;
            qr[4*i+1] = v.y * 0.125f;
            qr[4*i+2] = v.z * 0.125f;
            qr[4*i+3] = v.w * 0.125f;
        }
    }

    float m = -1e30f, l = 0.f;
    float acc[64];
    #pragma unroll
    for (int d = 0; d < 64; ++d) acc[d] = 0.f;

    for (int t = 0; t < SEQ / KTILE; ++t) {
        int k0 = t * KTILE;
        __syncthreads();
        for (int i = tid; i < KTILE * 16; i += 128) {
            int r  = i >> 4;
            int c4 = (i & 15) << 2;
            const float* trow = base + (size_t)(k0 + r) * QKVC + hq;
            *(float4*)&Ks[r * 64 + c4] = *(const float4*)(trow + EMBED + c4);
            *(float4*)&Vs[r * 64 + c4] = *(const float4*)(trow + 2 * EMBED + c4);
        }
        __syncthreads();

        for (int k = 0; k < KTILE; ++k) {
            float s0 = 0.f, s1 = 0.f, s2 = 0.f, s3 = 0.f;
            #pragma unroll
            for (int d4 = 0; d4 < 16; ++d4) {
                float4 kv = *(const float4*)&Ks[k * 64 + d4 * 4];
                s0 += qr[d4*4+0] * kv.x;
                s1 += qr[d4*4+1] * kv.y;
                s2 += qr[d4*4+2] * kv.z;
                s3 += qr[d4*4+3] * kv.w;
            }
            float s = (s0 + s1) + (s2 + s3);

            if (s > m) {
                float corr = __expf(m - s);
                l *= corr;
                #pragma unroll
                for (int d = 0; d < 64; ++d) acc[d] *= corr;
                m = s;
            }
            float p = __expf(s - m);
            l += p;
            #pragma unroll
            for (int d4 = 0; d4 < 16; ++d4) {
                float4 vv = *(const float4*)&Vs[k * 64 + d4 * 4];
                acc[d4*4+0] += p * vv.x;
                acc[d4*4+1] += p * vv.y;
                acc[d4*4+2] += p * vv.z;
                acc[d4*4+3] += p * vv.w;
            }
        }
    }

    float inv = 1.0f / l;
    __nv_bfloat16* orow = ctxs + ((size_t)(b * SEQ) + q) * EMBED + hq;
    #pragma unroll
    for (int d = 0; d < 64; d += 2) {
        __nv_bfloat162 p;
        p.x = __float2bfloat16(acc[d] * inv);
        p.y = __float2bfloat16(acc[d + 1] * inv);
        *(__nv_bfloat162*)&orow[d] = p;
    }
}

// ---------------------------------------------------------------------------
// Launch
// ---------------------------------------------------------------------------
extern "C" void kernel_launch(void* const* d_in, const int* in_sizes, int n_in,
                              void* d_out, int out_size)
{
    const float* x      = (const float*)d_in[0];
    const float* ln1_g  = (const float*)d_in[1];
    const float* ln1_b  = (const float*)d_in[2];
    const float* qkv_w  = (const float*)d_in[3];
    const float* qkv_b  = (const float*)d_in[4];
    const float* proj_w = (const float*)d_in[5];
    const float* proj_b = (const float*)d_in[6];
    const float* ln2_g  = (const float*)d_in[7];
    const float* ln2_b  = (const float*)d_in[8];
    const float* fc1_w  = (const float*)d_in[9];
    const float* fc1_b  = (const float*)d_in[10];
    const float* fc2_w  = (const float*)d_in[11];
    const float* fc2_b  = (const float*)d_in[12];
    float* out = (float*)d_out;

    float *p_qkv, *p_x1;
    __nv_bfloat16 *p_as, *p_ctxs, *p_f1s, *p_wq, *p_wp, *p_w1, *p_w2;
    cudaGetSymbolAddress((void**)&p_qkv,  g_qkv);
    cudaGetSymbolAddress((void**)&p_x1,   g_x1);
    cudaGetSymbolAddress((void**)&p_as,   g_as);
    cudaGetSymbolAddress((void**)&p_ctxs, g_ctxs);
    cudaGetSymbolAddress((void**)&p_f1s,  g_f1s);
    cudaGetSymbolAddress((void**)&p_wq,   g_wq);
    cudaGetSymbolAddress((void**)&p_wp,   g_wp);
    cudaGetSymbolAddress((void**)&p_w1,   g_w1);
    cudaGetSymbolAddress((void**)&p_w2,   g_w2);

    // weight conversions (graph-replayed, deterministic)
    wconv_kernel<<<512, 256>>>(qkv_w,  p_wq, (size_t)QKVC  * EMBED);
    wconv_kernel<<<512, 256>>>(proj_w, p_wp, (size_t)EMBED * EMBED);
    wconv_kernel<<<512, 256>>>(fc1_w,  p_w1, (size_t)HIDDEN * EMBED);
    wconv_kernel<<<512, 256>>>(fc2_w,  p_w2, (size_t)EMBED * HIDDEN);

    // 1) LN1 -> bf16
    ln_kernel<<<MTOK, 256>>>(x, ln1_g, ln1_b, p_as);
    // 2) QKV GEMM (tensor) -> fp32 qkv
    tc_gemm<0><<<dim3(QKVC / 128, MTOK / 128), 256>>>(
        p_as, p_wq, qkv_b, nullptr, p_qkv, nullptr, QKVC, EMBED);
    // 3) attention -> bf16 ctx
    attn_kernel<<<dim3(SEQ / 128, BATCH * HEADS), 128>>>(p_qkv, p_ctxs);
    // 4) proj GEMM + residual -> fp32 x1
    tc_gemm<1><<<dim3(EMBED / 128, MTOK / 128), 256>>>(
        p_ctxs, p_wp, proj_b, x, p_x1, nullptr, EMBED, EMBED);
    // 5) LN2 -> bf16
    ln_kernel<<<MTOK, 256>>>(p_x1, ln2_g, ln2_b, p_as);
    // 6) FC1 GEMM + GELU -> bf16
    tc_gemm<2><<<dim3(HIDDEN / 128, MTOK / 128), 256>>>(
        p_as, p_w1, fc1_b, nullptr, nullptr, p_f1s, HIDDEN, EMBED);
    // 7) FC2 GEMM + residual -> final fp32 output
    tc_gemm<1><<<dim3(EMBED / 128, MTOK / 128), 256>>>(
        p_f1s, p_w2, fc2_b, p_x1, out, nullptr, EMBED, HIDDEN);
}

// round 10
// speedup vs baseline: 4.7551x; 1.9800x over previous
#include <cuda_runtime.h>
#include <cuda_bf16.h>
#include <mma.h>
#include <math.h>
#include <stdint.h>

using namespace nvcuda;

// ---------------------------------------------------------------------------
// Problem constants
// ---------------------------------------------------------------------------
#define BATCH   8
#define SEQ     1024
#define EMBED   768
#define HEADS   12
#define HD      64
#define HIDDEN  3072
#define MTOK    (BATCH * SEQ)          // 8192 tokens
#define QKVC    (3 * EMBED)            // 2304

// ---------------------------------------------------------------------------
// Scratch (static __device__: allocation-free per harness rules)
// ---------------------------------------------------------------------------
__device__ __align__(16) float         g_qkv [(size_t)MTOK * QKVC];
__device__ __align__(16) float         g_x1  [(size_t)MTOK * EMBED];
__device__ __align__(16) __nv_bfloat16 g_as  [(size_t)MTOK * EMBED];    // LN out (reused)
__device__ __align__(16) __nv_bfloat16 g_ctxs[(size_t)MTOK * EMBED];    // attn ctx
__device__ __align__(16) __nv_bfloat16 g_f1s [(size_t)MTOK * HIDDEN];   // gelu(fc1)
__device__ __align__(16) __nv_bfloat16 g_wq  [(size_t)QKVC  * EMBED];
__device__ __align__(16) __nv_bfloat16 g_wp  [(size_t)EMBED * EMBED];
__device__ __align__(16) __nv_bfloat16 g_w1  [(size_t)HIDDEN* EMBED];
__device__ __align__(16) __nv_bfloat16 g_w2  [(size_t)EMBED * HIDDEN];

// ---------------------------------------------------------------------------
// Weight convert: fp32 -> bf16
// ---------------------------------------------------------------------------
__global__ void wconv_kernel(const float* __restrict__ W, __nv_bfloat16* __restrict__ out,
                             size_t total)
{
    size_t i = ((size_t)blockIdx.x * blockDim.x + threadIdx.x) * 4;
    size_t stride = (size_t)gridDim.x * blockDim.x * 4;
    for (; i < total; i += stride) {
        float4 v = *(const float4*)&W[i];
        __nv_bfloat162 p0, p1;
        p0.x = __float2bfloat16(v.x); p0.y = __float2bfloat16(v.y);
        p1.x = __float2bfloat16(v.z); p1.y = __float2bfloat16(v.w);
        *(__nv_bfloat162*)&out[i]     = p0;
        *(__nv_bfloat162*)&out[i + 2] = p1;
    }
}

// ---------------------------------------------------------------------------
// LayerNorm -> bf16 row (768)
// ---------------------------------------------------------------------------
__global__ __launch_bounds__(256) void ln_kernel(
    const float* __restrict__ x, const float* __restrict__ g,
    const float* __restrict__ bvec, __nv_bfloat16* __restrict__ out)
{
    int row = blockIdx.x;
    const float* xr = x + (size_t)row * EMBED;
    int t = threadIdx.x;

    float v0 = xr[t], v1 = xr[t + 256], v2 = xr[t + 512];
    float s  = v0 + v1 + v2;
    float ss = v0 * v0 + v1 * v1 + v2 * v2;

    __shared__ float red0[8], red1[8];
    int lane = t & 31, wid = t >> 5;
    #pragma unroll
    for (int o = 16; o; o >>= 1) {
        s  += __shfl_xor_sync(0xffffffffu, s,  o);
        ss += __shfl_xor_sync(0xffffffffu, ss, o);
    }
    if (lane == 0) { red0[wid] = s; red1[wid] = ss; }
    __syncthreads();
    if (t < 32) {
        s  = (t < 8) ? red0[t] : 0.f;
        ss = (t < 8) ? red1[t] : 0.f;
        #pragma unroll
        for (int o = 4; o; o >>= 1) {
            s  += __shfl_xor_sync(0xffffffffu, s,  o);
            ss += __shfl_xor_sync(0xffffffffu, ss, o);
        }
        if (t == 0) { red0[0] = s; red1[0] = ss; }
    }
    __syncthreads();
    float mean = red0[0] * (1.0f / EMBED);
    float var  = red1[0] * (1.0f / EMBED) - mean * mean;
    float rstd = rsqrtf(var + 1e-5f);

    __nv_bfloat16* orow = out + (size_t)row * EMBED;
    orow[t]       = __float2bfloat16((v0 - mean) * rstd * g[t]       + bvec[t]);
    orow[t + 256] = __float2bfloat16((v1 - mean) * rstd * g[t + 256] + bvec[t + 256]);
    orow[t + 512] = __float2bfloat16((v2 - mean) * rstd * g[t + 512] + bvec[t + 512]);
}

// ---------------------------------------------------------------------------
// WMMA bf16 GEMM (validated R8): C[M,N] = A[M,K] * B[N,K]^T (+bias, epilogue)
// ---------------------------------------------------------------------------
#define LDS 40

template<int EPI>
__global__ __launch_bounds__(256) void tc_gemm(
    const __nv_bfloat16* __restrict__ A, const __nv_bfloat16* __restrict__ B,
    const float* __restrict__ bias, const float* __restrict__ Res,
    float* __restrict__ C, __nv_bfloat16* __restrict__ Cs,
    int N, int Kp)
{
    __shared__ __align__(16) __nv_bfloat16 As[2][128 * LDS];
    __shared__ __align__(16) __nv_bfloat16 Bs[2][128 * LDS];

    int tid  = threadIdx.x;
    int warp = tid >> 5, lane = tid & 31;
    int wm = warp >> 1, wn = warp & 1;
    int bm = blockIdx.y * 128, bn = blockIdx.x * 128;

    int grow = tid >> 2;
    int gcol = (tid & 3) << 3;
    const __nv_bfloat16* Ag = A + (size_t)(bm + grow) * Kp + gcol;
    const __nv_bfloat16* Bg = B + (size_t)(bn + grow) * Kp + gcol;
    const size_t half = (size_t)64 * Kp;

    wmma::fragment<wmma::accumulator, 16, 16, 16, float> acc[2][4];
    #pragma unroll
    for (int i = 0; i < 2; ++i)
        #pragma unroll
        for (int j = 0; j < 4; ++j) wmma::fill_fragment(acc[i][j], 0.0f);

    int nk = Kp >> 5;
    float4 ra0, ra1, rb0, rb1;

    ra0 = *(const float4*)(Ag);        ra1 = *(const float4*)(Ag + half);
    rb0 = *(const float4*)(Bg);        rb1 = *(const float4*)(Bg + half);

    for (int t = 0; t < nk; ++t) {
        int st = t & 1;
        *(float4*)&As[st][grow * LDS + gcol]        = ra0;
        *(float4*)&As[st][(grow + 64) * LDS + gcol] = ra1;
        *(float4*)&Bs[st][grow * LDS + gcol]        = rb0;
        *(float4*)&Bs[st][(grow + 64) * LDS + gcol] = rb1;
        __syncthreads();

        if (t + 1 < nk) {
            const __nv_bfloat16* An = Ag + ((t + 1) << 5);
            const __nv_bfloat16* Bn = Bg + ((t + 1) << 5);
            ra0 = *(const float4*)(An);      ra1 = *(const float4*)(An + half);
            rb0 = *(const float4*)(Bn);      rb1 = *(const float4*)(Bn + half);
        }

        #pragma unroll
        for (int ks = 0; ks < 2; ++ks) {
            wmma::fragment<wmma::matrix_a, 16, 16, 16, __nv_bfloat16, wmma::row_major> af[2];
            wmma::fragment<wmma::matrix_b, 16, 16, 16, __nv_bfloat16, wmma::col_major> bf[4];
            #pragma unroll
            for (int i = 0; i < 2; ++i)
                wmma::load_matrix_sync(af[i], &As[st][(wm * 32 + i * 16) * LDS + ks * 16], LDS);
            #pragma unroll
            for (int j = 0; j < 4; ++j)
                wmma::load_matrix_sync(bf[j], &Bs[st][(wn * 64 + j * 16) * LDS + ks * 16], LDS);
            #pragma unroll
            for (int i = 0; i < 2; ++i)
                #pragma unroll
                for (int j = 0; j < 4; ++j)
                    wmma::mma_sync(acc[i][j], af[i], bf[j], acc[i][j]);
        }
        __syncthreads();
    }

    float* stage = reinterpret_cast<float*>(&As[0][0]);
    float* ws = stage + warp * 256;
    int er = lane >> 1, ec = (lane & 1) << 3;

    #pragma unroll
    for (int i = 0; i < 2; ++i) {
        #pragma unroll
        for (int j = 0; j < 4; ++j) {
            wmma::store_matrix_sync(ws, acc[i][j], 16, wmma::mem_row_major);
            __syncwarp();
            int row = bm + wm * 32 + i * 16 + er;
            int col = bn + wn * 64 + j * 16 + ec;
            float v[8];
            #pragma unroll
            for (int u = 0; u < 8; ++u) v[u] = ws[er * 16 + ec + u] + bias[col + u];
            if (EPI == 2) {
                size_t off = (size_t)row * N + col;
                #pragma unroll
                for (int u = 0; u < 8; u += 2) {
                    float g0 = 0.5f * v[u]     * (1.0f + erff(v[u]     * 0.70710678118654752f));
                    float g1 = 0.5f * v[u + 1] * (1.0f + erff(v[u + 1] * 0.70710678118654752f));
                    __nv_bfloat162 p;
                    p.x = __float2bfloat16(g0);
                    p.y = __float2bfloat16(g1);
                    *(__nv_bfloat162*)&Cs[off + u] = p;
                }
            } else {
                size_t off = (size_t)row * N + col;
                if (EPI == 1) {
                    float4 r0 = *(const float4*)&Res[off];
                    float4 r1 = *(const float4*)&Res[off + 4];
                    v[0] += r0.x; v[1] += r0.y; v[2] += r0.z; v[3] += r0.w;
                    v[4] += r1.x; v[5] += r1.y; v[6] += r1.z; v[7] += r1.w;
                }
                *(float4*)&C[off]     = make_float4(v[0], v[1], v[2], v[3]);
                *(float4*)&C[off + 4] = make_float4(v[4], v[5], v[6], v[7]);
            }
            __syncwarp();
        }
    }
}

// ---------------------------------------------------------------------------
// FlashAttention-2 style fused attention, mma.sync.m16n8k16 bf16 / fp32 acc.
// grid = (SEQ/64, BATCH*HEADS), block = 128 (4 warps x 16 queries).
// All fragment layouts per documented PTX m16n8k16 mappings:
//   acc:  c0=(r,c) c1=(r,c+1) c2=(r+8,c) c3=(r+8,c+1), r=lane/4, c=(lane%4)*2
//   A:    a0=(r,k) a1=(r+8,k) a2=(r,k+8) a3=(r+8,k+8), k=(lane%4)*2
//   B:    b0=(k,n) k=(lane%4)*2+{0,1}, n=lane/4; b1: k+8
// S-acc frags re-pack directly into P A-frags (layout identity at k=16).
// ---------------------------------------------------------------------------
#define AST 72   // smem row stride (bf16 elems): 144B -> conflict-free ldmatrix

__device__ __forceinline__ void ldm4(uint32_t* r, uint32_t addr) {
    asm volatile("ldmatrix.sync.aligned.m8n8.x4.shared.b16 {%0,%1,%2,%3}, [%4];"
        : "=r"(r[0]), "=r"(r[1]), "=r"(r[2]), "=r"(r[3]) : "r"(addr));
}
__device__ __forceinline__ void ldm4t(uint32_t* r, uint32_t addr) {
    asm volatile("ldmatrix.sync.aligned.m8n8.x4.trans.shared.b16 {%0,%1,%2,%3}, [%4];"
        : "=r"(r[0]), "=r"(r[1]), "=r"(r[2]), "=r"(r[3]) : "r"(addr));
}
__device__ __forceinline__ void mma16816(float* c, const uint32_t* a, uint32_t b0, uint32_t b1) {
    asm volatile("mma.sync.aligned.m16n8k16.row.col.f32.bf16.bf16.f32 "
        "{%0,%1,%2,%3}, {%4,%5,%6,%7}, {%8,%9}, {%0,%1,%2,%3};"
        : "+f"(c[0]), "+f"(c[1]), "+f"(c[2]), "+f"(c[3])
        : "r"(a[0]), "r"(a[1]), "r"(a[2]), "r"(a[3]), "r"(b0), "r"(b1));
}
__device__ __forceinline__ uint32_t packbf(float lo, float hi) {
    __nv_bfloat162 t = __floats2bfloat162_rn(lo, hi);   // x=lo, y=hi
    return *(uint32_t*)&t;
}

__global__ __launch_bounds__(128) void attn_kernel(
    const float* __restrict__ qkv, __nv_bfloat16* __restrict__ ctxs)
{
    __shared__ __align__(16) __nv_bfloat16 Qs[64 * AST];
    __shared__ __align__(16) __nv_bfloat16 Ks[64 * AST];
    __shared__ __align__(16) __nv_bfloat16 Vs[64 * AST];

    int bh = blockIdx.y;
    int b  = bh / HEADS;
    int h  = bh % HEADS;
    int q0 = blockIdx.x * 64;
    int tid = threadIdx.x, warp = tid >> 5, lane = tid & 31;
    int hq = h * HD;
    const float* base = qkv + (size_t)(b * SEQ) * QKVC;

    // ---- load Q tile (pre-scaled by 1/8, exact pow2) -> bf16 smem ----
    for (int i = tid; i < 1024; i += 128) {
        int r = i >> 4, c4 = (i & 15) << 2;
        float4 v = *(const float4*)(base + (size_t)(q0 + r) * QKVC + hq + c4);
        *(__nv_bfloat162*)&Qs[r * AST + c4]     = __floats2bfloat162_rn(v.x * 0.125f, v.y * 0.125f);
        *(__nv_bfloat162*)&Qs[r * AST + c4 + 2] = __floats2bfloat162_rn(v.z * 0.125f, v.w * 0.125f);
    }
    __syncthreads();

    // ---- Q A-frags, register-resident for the whole kernel ----
    uint32_t qa[4][4];
    {
        int qr = warp * 16 + (lane & 15);
        int cb = (lane >> 4) << 3;
        #pragma unroll
        for (int kk = 0; kk < 4; ++kk)
            ldm4(qa[kk], (uint32_t)__cvta_generic_to_shared(&Qs[qr * AST + kk * 16 + cb]));
    }

    float o[8][4];
    #pragma unroll
    for (int j = 0; j < 8; ++j)
        #pragma unroll
        for (int c = 0; c < 4; ++c) o[j][c] = 0.f;
    float mA = -1e30f, mB = -1e30f, lA = 0.f, lB = 0.f;

    // precomputed ldmatrix lane-address components
    int krow = ((lane >> 4) << 3) + (lane & 7);   // key-row selector for K frags
    int kcb  = (lane & 8);                         // +8 col for b1 half
    int vrow = (lane & 15);                        // key-row selector for V frags
    int vcb  = (lane >> 4) << 3;                   // +8 dim col selector

    for (int t = 0; t < 16; ++t) {
        __syncthreads();
        // ---- load K,V tile (fp32 -> bf16) ----
        for (int i = tid; i < 1024; i += 128) {
            int r = i >> 4, c4 = (i & 15) << 2;
            const float* trow = base + (size_t)(t * 64 + r) * QKVC + hq;
            float4 kv = *(const float4*)(trow + EMBED + c4);
            float4 vv = *(const float4*)(trow + 2 * EMBED + c4);
            *(__nv_bfloat162*)&Ks[r * AST + c4]     = __floats2bfloat162_rn(kv.x, kv.y);
            *(__nv_bfloat162*)&Ks[r * AST + c4 + 2] = __floats2bfloat162_rn(kv.z, kv.w);
            *(__nv_bfloat162*)&Vs[r * AST + c4]     = __floats2bfloat162_rn(vv.x, vv.y);
            *(__nv_bfloat162*)&Vs[r * AST + c4 + 2] = __floats2bfloat162_rn(vv.z, vv.w);
        }
        __syncthreads();

        // ---- S = Q K^T : 8 n-frags (8 keys each) x 4 k-steps ----
        float s[8][4];
        #pragma unroll
        for (int j = 0; j < 8; ++j)
            #pragma unroll
            for (int c = 0; c < 4; ++c) s[j][c] = 0.f;
        #pragma unroll
        for (int kk = 0; kk < 4; ++kk) {
            #pragma unroll
            for (int j = 0; j < 8; j += 2) {
                uint32_t kb[4];
                ldm4(kb, (uint32_t)__cvta_generic_to_shared(
                    &Ks[(j * 8 + krow) * AST + kk * 16 + kcb]));
                mma16816(s[j],     qa[kk], kb[0], kb[1]);
                mma16816(s[j + 1], qa[kk], kb[2], kb[3]);
            }
        }

        // ---- online softmax (rows lane/4 and lane/4+8) ----
        float rmA = -1e30f, rmB = -1e30f;
        #pragma unroll
        for (int j = 0; j < 8; ++j) {
            rmA = fmaxf(rmA, fmaxf(s[j][0], s[j][1]));
            rmB = fmaxf(rmB, fmaxf(s[j][2], s[j][3]));
        }
        rmA = fmaxf(rmA, __shfl_xor_sync(0xffffffffu, rmA, 1));
        rmA = fmaxf(rmA, __shfl_xor_sync(0xffffffffu, rmA, 2));
        rmB = fmaxf(rmB, __shfl_xor_sync(0xffffffffu, rmB, 1));
        rmB = fmaxf(rmB, __shfl_xor_sync(0xffffffffu, rmB, 2));
        float mnA = fmaxf(mA, rmA), mnB = fmaxf(mB, rmB);
        float corrA = __expf(mA - mnA), corrB = __expf(mB - mnB);
        mA = mnA; mB = mnB;

        float rsA = 0.f, rsB = 0.f;
        #pragma unroll
        for (int j = 0; j < 8; ++j) {
            s[j][0] = __expf(s[j][0] - mA);
            s[j][1] = __expf(s[j][1] - mA);
            s[j][2] = __expf(s[j][2] - mB);
            s[j][3] = __expf(s[j][3] - mB);
            rsA += s[j][0] + s[j][1];
            rsB += s[j][2] + s[j][3];
        }
        rsA += __shfl_xor_sync(0xffffffffu, rsA, 1);
        rsA += __shfl_xor_sync(0xffffffffu, rsA, 2);
        rsB += __shfl_xor_sync(0xffffffffu, rsB, 1);
        rsB += __shfl_xor_sync(0xffffffffu, rsB, 2);
        lA = lA * corrA + rsA;
        lB = lB * corrB + rsB;
        #pragma unroll
        for (int j = 0; j < 8; ++j) {
            o[j][0] *= corrA; o[j][1] *= corrA;
            o[j][2] *= corrB; o[j][3] *= corrB;
        }

        // ---- P frags (acc->A layout identity) + PV ----
        uint32_t pa[4][4];
        #pragma unroll
        for (int kk = 0; kk < 4; ++kk) {
            pa[kk][0] = packbf(s[2 * kk][0],     s[2 * kk][1]);
            pa[kk][1] = packbf(s[2 * kk][2],     s[2 * kk][3]);
            pa[kk][2] = packbf(s[2 * kk + 1][0], s[2 * kk + 1][1]);
            pa[kk][3] = packbf(s[2 * kk + 1][2], s[2 * kk + 1][3]);
        }
        #pragma unroll
        for (int kk = 0; kk < 4; ++kk) {
            #pragma unroll
            for (int d8 = 0; d8 < 8; d8 += 2) {
                uint32_t vb[4];
                ldm4t(vb, (uint32_t)__cvta_generic_to_shared(
                    &Vs[(16 * kk + vrow) * AST + d8 * 8 + vcb]));
                mma16816(o[d8],     pa[kk], vb[0], vb[1]);
                mma16816(o[d8 + 1], pa[kk], vb[2], vb[3]);
            }
        }
    }

    // ---- finalize: o / l, write bf16 ctx ----
    float iA = 1.0f / lA, iB = 1.0f / lB;
    int rowA = lane >> 2;
    int qA = q0 + warp * 16 + rowA;
    int cA = hq + (lane & 3) * 2;
    __nv_bfloat16* outA = ctxs + ((size_t)(b * SEQ) + qA) * EMBED;
    __nv_bfloat16* outB = outA + (size_t)8 * EMBED;
    #pragma unroll
    for (int j = 0; j < 8; ++j) {
        *(uint32_t*)&outA[cA + j * 8] = packbf(o[j][0] * iA, o[j][1] * iA);
        *(uint32_t*)&outB[cA + j * 8] = packbf(o[j][2] * iB, o[j][3] * iB);
    }
}

// ---------------------------------------------------------------------------
// Launch
// ---------------------------------------------------------------------------
extern "C" void kernel_launch(void* const* d_in, const int* in_sizes, int n_in,
                              void* d_out, int out_size)
{
    const float* x      = (const float*)d_in[0];
    const float* ln1_g  = (const float*)d_in[1];
    const float* ln1_b  = (const float*)d_in[2];
    const float* qkv_w  = (const float*)d_in[3];
    const float* qkv_b  = (const float*)d_in[4];
    const float* proj_w = (const float*)d_in[5];
    const float* proj_b = (const float*)d_in[6];
    const float* ln2_g  = (const float*)d_in[7];
    const float* ln2_b  = (const float*)d_in[8];
    const float* fc1_w  = (const float*)d_in[9];
    const float* fc1_b  = (const float*)d_in[10];
    const float* fc2_w  = (const float*)d_in[11];
    const float* fc2_b  = (const float*)d_in[12];
    float* out = (float*)d_out;

    float *p_qkv, *p_x1;
    __nv_bfloat16 *p_as, *p_ctxs, *p_f1s, *p_wq, *p_wp, *p_w1, *p_w2;
    cudaGetSymbolAddress((void**)&p_qkv,  g_qkv);
    cudaGetSymbolAddress((void**)&p_x1,   g_x1);
    cudaGetSymbolAddress((void**)&p_as,   g_as);
    cudaGetSymbolAddress((void**)&p_ctxs, g_ctxs);
    cudaGetSymbolAddress((void**)&p_f1s,  g_f1s);
    cudaGetSymbolAddress((void**)&p_wq,   g_wq);
    cudaGetSymbolAddress((void**)&p_wp,   g_wp);
    cudaGetSymbolAddress((void**)&p_w1,   g_w1);
    cudaGetSymbolAddress((void**)&p_w2,   g_w2);

    wconv_kernel<<<512, 256>>>(qkv_w,  p_wq, (size_t)QKVC  * EMBED);
    wconv_kernel<<<512, 256>>>(proj_w, p_wp, (size_t)EMBED * EMBED);
    wconv_kernel<<<512, 256>>>(fc1_w,  p_w1, (size_t)HIDDEN * EMBED);
    wconv_kernel<<<512, 256>>>(fc2_w,  p_w2, (size_t)EMBED * HIDDEN);

    // 1) LN1 -> bf16
    ln_kernel<<<MTOK, 256>>>(x, ln1_g, ln1_b, p_as);
    // 2) QKV GEMM -> fp32
    tc_gemm<0><<<dim3(QKVC / 128, MTOK / 128), 256>>>(
        p_as, p_wq, qkv_b, nullptr, p_qkv, nullptr, QKVC, EMBED);
    // 3) flash attention (tensor cores) -> bf16 ctx
    attn_kernel<<<dim3(SEQ / 64, BATCH * HEADS), 128>>>(p_qkv, p_ctxs);
    // 4) proj GEMM + residual -> fp32 x1
    tc_gemm<1><<<dim3(EMBED / 128, MTOK / 128), 256>>>(
        p_ctxs, p_wp, proj_b, x, p_x1, nullptr, EMBED, EMBED);
    // 5) LN2 -> bf16
    ln_kernel<<<MTOK, 256>>>(p_x1, ln2_g, ln2_b, p_as);
    // 6) FC1 GEMM + GELU -> bf16
    tc_gemm<2><<<dim3(HIDDEN / 128, MTOK / 128), 256>>>(
        p_as, p_w1, fc1_b, nullptr, nullptr, p_f1s, HIDDEN, EMBED);
    // 7) FC2 GEMM + residual -> final fp32 output
    tc_gemm<1><<<dim3(EMBED / 128, MTOK / 128), 256>>>(
        p_f1s, p_w2, fc2_b, p_x1, out, nullptr, EMBED, HIDDEN);
}

// round 11
// speedup vs baseline: 4.9494x; 1.0409x over previous
#include <cuda_runtime.h>
#include <cuda_bf16.h>
#include <mma.h>
#include <math.h>
#include <stdint.h>

using namespace nvcuda;

// ---------------------------------------------------------------------------
// Problem constants
// ---------------------------------------------------------------------------
#define BATCH   8
#define SEQ     1024
#define EMBED   768
#define HEADS   12
#define HD      64
#define HIDDEN  3072
#define MTOK    (BATCH * SEQ)          // 8192 tokens
#define QKVC    (3 * EMBED)            // 2304

// ---------------------------------------------------------------------------
// Scratch (static __device__: allocation-free per harness rules)
// ---------------------------------------------------------------------------
__device__ __align__(16) float         g_qkv [(size_t)MTOK * QKVC];
__device__ __align__(16) float         g_x1  [(size_t)MTOK * EMBED];
__device__ __align__(16) __nv_bfloat16 g_as  [(size_t)MTOK * EMBED];    // LN out (reused)
__device__ __align__(16) __nv_bfloat16 g_ctxs[(size_t)MTOK * EMBED];    // attn ctx
__device__ __align__(16) __nv_bfloat16 g_f1s [(size_t)MTOK * HIDDEN];   // gelu(fc1)
__device__ __align__(16) __nv_bfloat16 g_wq  [(size_t)QKVC  * EMBED];
__device__ __align__(16) __nv_bfloat16 g_wp  [(size_t)EMBED * EMBED];
__device__ __align__(16) __nv_bfloat16 g_w1  [(size_t)HIDDEN* EMBED];
__device__ __align__(16) __nv_bfloat16 g_w2  [(size_t)EMBED * HIDDEN];

// ---------------------------------------------------------------------------
// Fused weight convert: all four weight tensors fp32 -> bf16 in one launch
// ---------------------------------------------------------------------------
#define WQ_N ((size_t)QKVC  * EMBED)    // 1769472
#define WP_N ((size_t)EMBED * EMBED)    //  589824
#define W1_N ((size_t)HIDDEN * EMBED)   // 2359296
#define W2_N ((size_t)EMBED * HIDDEN)   // 2359296

__global__ void wconv_all(const float* __restrict__ wq, const float* __restrict__ wp,
                          const float* __restrict__ w1, const float* __restrict__ w2,
                          __nv_bfloat16* __restrict__ oq, __nv_bfloat16* __restrict__ op,
                          __nv_bfloat16* __restrict__ o1, __nv_bfloat16* __restrict__ o2)
{
    const size_t total = WQ_N + WP_N + W1_N + W2_N;
    size_t i = ((size_t)blockIdx.x * blockDim.x + threadIdx.x) * 4;
    size_t stride = (size_t)gridDim.x * blockDim.x * 4;
    for (; i < total; i += stride) {
        const float* src; __nv_bfloat16* dst; size_t off = i;
        if (off < WQ_N)                         { src = wq; dst = oq; }
        else if ((off -= WQ_N) < WP_N)          { src = wp; dst = op; }
        else if ((off -= WP_N) < W1_N)          { src = w1; dst = o1; }
        else { off -= W1_N;                       src = w2; dst = o2; }
        float4 v = *(const float4*)&src[off];
        __nv_bfloat162 p0, p1;
        p0.x = __float2bfloat16(v.x); p0.y = __float2bfloat16(v.y);
        p1.x = __float2bfloat16(v.z); p1.y = __float2bfloat16(v.w);
        *(__nv_bfloat162*)&dst[off]     = p0;
        *(__nv_bfloat162*)&dst[off + 2] = p1;
    }
}

// ---------------------------------------------------------------------------
// LayerNorm -> bf16 row (768)
// ---------------------------------------------------------------------------
__global__ __launch_bounds__(256) void ln_kernel(
    const float* __restrict__ x, const float* __restrict__ g,
    const float* __restrict__ bvec, __nv_bfloat16* __restrict__ out)
{
    int row = blockIdx.x;
    const float* xr = x + (size_t)row * EMBED;
    int t = threadIdx.x;

    float v0 = xr[t], v1 = xr[t + 256], v2 = xr[t + 512];
    float s  = v0 + v1 + v2;
    float ss = v0 * v0 + v1 * v1 + v2 * v2;

    __shared__ float red0[8], red1[8];
    int lane = t & 31, wid = t >> 5;
    #pragma unroll
    for (int o = 16; o; o >>= 1) {
        s  += __shfl_xor_sync(0xffffffffu, s,  o);
        ss += __shfl_xor_sync(0xffffffffu, ss, o);
    }
    if (lane == 0) { red0[wid] = s; red1[wid] = ss; }
    __syncthreads();
    if (t < 32) {
        s  = (t < 8) ? red0[t] : 0.f;
        ss = (t < 8) ? red1[t] : 0.f;
        #pragma unroll
        for (int o = 4; o; o >>= 1) {
            s  += __shfl_xor_sync(0xffffffffu, s,  o);
            ss += __shfl_xor_sync(0xffffffffu, ss, o);
        }
        if (t == 0) { red0[0] = s; red1[0] = ss; }
    }
    __syncthreads();
    float mean = red0[0] * (1.0f / EMBED);
    float var  = red1[0] * (1.0f / EMBED) - mean * mean;
    float rstd = rsqrtf(var + 1e-5f);

    __nv_bfloat16* orow = out + (size_t)row * EMBED;
    orow[t]       = __float2bfloat16((v0 - mean) * rstd * g[t]       + bvec[t]);
    orow[t + 256] = __float2bfloat16((v1 - mean) * rstd * g[t + 256] + bvec[t + 256]);
    orow[t + 512] = __float2bfloat16((v2 - mean) * rstd * g[t + 512] + bvec[t + 512]);
}

// ---------------------------------------------------------------------------
// WMMA bf16 GEMM with cp.async 3-stage pipeline.
// C[M,N] = A[M,K] * B[N,K]^T (+bias, epilogue), fp32 accum.
// 128x128 tile, 256 thr (8 warps 4x2), warp 32x64, BK=32.
// EPI: 0 = bias -> fp32 C; 1 = bias+Res -> fp32 C; 2 = bias+GELU -> bf16 Cs
// ---------------------------------------------------------------------------
#define LDS 40
#define STAGES 3
#define STAGE_ELEMS (128 * LDS)                    // bf16 elems per stage per matrix
#define GEMM_SMEM (STAGES * 2 * STAGE_ELEMS * 2)   // bytes = 61440

__device__ __forceinline__ void cpasync16(uint32_t dst, const void* src) {
    asm volatile("cp.async.cg.shared.global [%0], [%1], 16;" :: "r"(dst), "l"(src));
}
__device__ __forceinline__ void cp_commit() {
    asm volatile("cp.async.commit_group;");
}
template<int N> __device__ __forceinline__ void cp_wait() {
    asm volatile("cp.async.wait_group %0;" :: "n"(N));
}

template<int EPI>
__global__ __launch_bounds__(256) void tc_gemm(
    const __nv_bfloat16* __restrict__ A, const __nv_bfloat16* __restrict__ B,
    const float* __restrict__ bias, const float* __restrict__ Res,
    float* __restrict__ C, __nv_bfloat16* __restrict__ Cs,
    int N, int Kp)
{
    extern __shared__ __align__(16) char dynsmem[];
    __nv_bfloat16* Asm = (__nv_bfloat16*)dynsmem;
    __nv_bfloat16* Bsm = Asm + STAGES * STAGE_ELEMS;
    uint32_t sAu = (uint32_t)__cvta_generic_to_shared(Asm);
    uint32_t sBu = (uint32_t)__cvta_generic_to_shared(Bsm);

    int tid  = threadIdx.x;
    int warp = tid >> 5, lane = tid & 31;
    int wm = warp >> 1, wn = warp & 1;
    int bm = blockIdx.y * 128, bn = blockIdx.x * 128;

    // cp.async mapping: each thread moves 2x16B per matrix per chunk
    int crow = tid >> 1;                 // 0..127
    int cseg = (tid & 1) << 1;           // 0 or 2 (16B segments)
    const __nv_bfloat16* Agp = A + (size_t)(bm + crow) * Kp + cseg * 8;
    const __nv_bfloat16* Bgp = B + (size_t)(bn + crow) * Kp + cseg * 8;
    uint32_t dstA = sAu + (crow * LDS + cseg * 8) * 2;
    uint32_t dstB = sBu + (crow * LDS + cseg * 8) * 2;

    auto load_chunk = [&](int chunk, int st) {
        uint32_t so = (uint32_t)st * STAGE_ELEMS * 2;
        const __nv_bfloat16* a = Agp + (chunk << 5);
        const __nv_bfloat16* b = Bgp + (chunk << 5);
        cpasync16(dstA + so,      a);
        cpasync16(dstA + so + 16, a + 8);
        cpasync16(dstB + so,      b);
        cpasync16(dstB + so + 16, b + 8);
    };

    wmma::fragment<wmma::accumulator, 16, 16, 16, float> acc[2][4];
    #pragma unroll
    for (int i = 0; i < 2; ++i)
        #pragma unroll
        for (int j = 0; j < 4; ++j) wmma::fill_fragment(acc[i][j], 0.0f);

    int nk = Kp >> 5;

    // prologue: STAGES-1 chunks in flight
    #pragma unroll
    for (int s = 0; s < STAGES - 1; ++s) {
        load_chunk(s, s);
        cp_commit();
    }

    for (int t = 0; t < nk; ++t) {
        cp_wait<STAGES - 2>();       // chunk t resident
        __syncthreads();             // visible to all; stage (t-1)%S free

        int nxt = t + STAGES - 1;
        if (nxt < nk) load_chunk(nxt, nxt % STAGES);
        cp_commit();                 // commit every iter (possibly empty group)

        int st = t % STAGES;
        __nv_bfloat16* Ast = Asm + st * STAGE_ELEMS;
        __nv_bfloat16* Bst = Bsm + st * STAGE_ELEMS;
        #pragma unroll
        for (int ks = 0; ks < 2; ++ks) {
            wmma::fragment<wmma::matrix_a, 16, 16, 16, __nv_bfloat16, wmma::row_major> af[2];
            wmma::fragment<wmma::matrix_b, 16, 16, 16, __nv_bfloat16, wmma::col_major> bf[4];
            #pragma unroll
            for (int i = 0; i < 2; ++i)
                wmma::load_matrix_sync(af[i], &Ast[(wm * 32 + i * 16) * LDS + ks * 16], LDS);
            #pragma unroll
            for (int j = 0; j < 4; ++j)
                wmma::load_matrix_sync(bf[j], &Bst[(wn * 64 + j * 16) * LDS + ks * 16], LDS);
            #pragma unroll
            for (int i = 0; i < 2; ++i)
                #pragma unroll
                for (int j = 0; j < 4; ++j)
                    wmma::mma_sync(acc[i][j], af[i], bf[j], acc[i][j]);
        }
    }
    __syncthreads();   // all warps done reading smem before staging reuse

    // ---- epilogue: stage each frag through smem, vector write ----
    float* stage = reinterpret_cast<float*>(dynsmem);
    float* ws = stage + warp * 256;
    int er = lane >> 1, ec = (lane & 1) << 3;

    #pragma unroll
    for (int i = 0; i < 2; ++i) {
        #pragma unroll
        for (int j = 0; j < 4; ++j) {
            wmma::store_matrix_sync(ws, acc[i][j], 16, wmma::mem_row_major);
            __syncwarp();
            int row = bm + wm * 32 + i * 16 + er;
            int col = bn + wn * 64 + j * 16 + ec;
            float v[8];
            #pragma unroll
            for (int u = 0; u < 8; ++u) v[u] = ws[er * 16 + ec + u] + bias[col + u];
            if (EPI == 2) {
                size_t off = (size_t)row * N + col;
                #pragma unroll
                for (int u = 0; u < 8; u += 2) {
                    float g0 = 0.5f * v[u]     * (1.0f + erff(v[u]     * 0.70710678118654752f));
                    float g1 = 0.5f * v[u + 1] * (1.0f + erff(v[u + 1] * 0.70710678118654752f));
                    __nv_bfloat162 p;
                    p.x = __float2bfloat16(g0);
                    p.y = __float2bfloat16(g1);
                    *(__nv_bfloat162*)&Cs[off + u] = p;
                }
            } else {
                size_t off = (size_t)row * N + col;
                if (EPI == 1) {
                    float4 r0 = *(const float4*)&Res[off];
                    float4 r1 = *(const float4*)&Res[off + 4];
                    v[0] += r0.x; v[1] += r0.y; v[2] += r0.z; v[3] += r0.w;
                    v[4] += r1.x; v[5] += r1.y; v[6] += r1.z; v[7] += r1.w;
                }
                *(float4*)&C[off]     = make_float4(v[0], v[1], v[2], v[3]);
                *(float4*)&C[off + 4] = make_float4(v[4], v[5], v[6], v[7]);
            }
            __syncwarp();
        }
    }
}

// ---------------------------------------------------------------------------
// FlashAttention-2 style fused attention (validated R10), mma.m16n8k16 bf16.
// ---------------------------------------------------------------------------
#define AST 72

__device__ __forceinline__ void ldm4(uint32_t* r, uint32_t addr) {
    asm volatile("ldmatrix.sync.aligned.m8n8.x4.shared.b16 {%0,%1,%2,%3}, [%4];"
        : "=r"(r[0]), "=r"(r[1]), "=r"(r[2]), "=r"(r[3]) : "r"(addr));
}
__device__ __forceinline__ void ldm4t(uint32_t* r, uint32_t addr) {
    asm volatile("ldmatrix.sync.aligned.m8n8.x4.trans.shared.b16 {%0,%1,%2,%3}, [%4];"
        : "=r"(r[0]), "=r"(r[1]), "=r"(r[2]), "=r"(r[3]) : "r"(addr));
}
__device__ __forceinline__ void mma16816(float* c, const uint32_t* a, uint32_t b0, uint32_t b1) {
    asm volatile("mma.sync.aligned.m16n8k16.row.col.f32.bf16.bf16.f32 "
        "{%0,%1,%2,%3}, {%4,%5,%6,%7}, {%8,%9}, {%0,%1,%2,%3};"
        : "+f"(c[0]), "+f"(c[1]), "+f"(c[2]), "+f"(c[3])
        : "r"(a[0]), "r"(a[1]), "r"(a[2]), "r"(a[3]), "r"(b0), "r"(b1));
}
__device__ __forceinline__ uint32_t packbf(float lo, float hi) {
    __nv_bfloat162 t = __floats2bfloat162_rn(lo, hi);
    return *(uint32_t*)&t;
}

__global__ __launch_bounds__(128) void attn_kernel(
    const float* __restrict__ qkv, __nv_bfloat16* __restrict__ ctxs)
{
    __shared__ __align__(16) __nv_bfloat16 Qs[64 * AST];
    __shared__ __align__(16) __nv_bfloat16 Ks[64 * AST];
    __shared__ __align__(16) __nv_bfloat16 Vs[64 * AST];

    int bh = blockIdx.y;
    int b  = bh / HEADS;
    int h  = bh % HEADS;
    int q0 = blockIdx.x * 64;
    int tid = threadIdx.x, warp = tid >> 5, lane = tid & 31;
    int hq = h * HD;
    const float* base = qkv + (size_t)(b * SEQ) * QKVC;

    for (int i = tid; i < 1024; i += 128) {
        int r = i >> 4, c4 = (i & 15) << 2;
        float4 v = *(const float4*)(base + (size_t)(q0 + r) * QKVC + hq + c4);
        *(__nv_bfloat162*)&Qs[r * AST + c4]     = __floats2bfloat162_rn(v.x * 0.125f, v.y * 0.125f);
        *(__nv_bfloat162*)&Qs[r * AST + c4 + 2] = __floats2bfloat162_rn(v.z * 0.125f, v.w * 0.125f);
    }
    __syncthreads();

    uint32_t qa[4][4];
    {
        int qr = warp * 16 + (lane & 15);
        int cb = (lane >> 4) << 3;
        #pragma unroll
        for (int kk = 0; kk < 4; ++kk)
            ldm4(qa[kk], (uint32_t)__cvta_generic_to_shared(&Qs[qr * AST + kk * 16 + cb]));
    }

    float o[8][4];
    #pragma unroll
    for (int j = 0; j < 8; ++j)
        #pragma unroll
        for (int c = 0; c < 4; ++c) o[j][c] = 0.f;
    float mA = -1e30f, mB = -1e30f, lA = 0.f, lB = 0.f;

    int krow = ((lane >> 4) << 3) + (lane & 7);
    int kcb  = (lane & 8);
    int vrow = (lane & 15);
    int vcb  = (lane >> 4) << 3;

    for (int t = 0; t < 16; ++t) {
        __syncthreads();
        for (int i = tid; i < 1024; i += 128) {
            int r = i >> 4, c4 = (i & 15) << 2;
            const float* trow = base + (size_t)(t * 64 + r) * QKVC + hq;
            float4 kv = *(const float4*)(trow + EMBED + c4);
            float4 vv = *(const float4*)(trow + 2 * EMBED + c4);
            *(__nv_bfloat162*)&Ks[r * AST + c4]     = __floats2bfloat162_rn(kv.x, kv.y);
            *(__nv_bfloat162*)&Ks[r * AST + c4 + 2] = __floats2bfloat162_rn(kv.z, kv.w);
            *(__nv_bfloat162*)&Vs[r * AST + c4]     = __floats2bfloat162_rn(vv.x, vv.y);
            *(__nv_bfloat162*)&Vs[r * AST + c4 + 2] = __floats2bfloat162_rn(vv.z, vv.w);
        }
        __syncthreads();

        float s[8][4];
        #pragma unroll
        for (int j = 0; j < 8; ++j)
            #pragma unroll
            for (int c = 0; c < 4; ++c) s[j][c] = 0.f;
        #pragma unroll
        for (int kk = 0; kk < 4; ++kk) {
            #pragma unroll
            for (int j = 0; j < 8; j += 2) {
                uint32_t kb[4];
                ldm4(kb, (uint32_t)__cvta_generic_to_shared(
                    &Ks[(j * 8 + krow) * AST + kk * 16 + kcb]));
                mma16816(s[j],     qa[kk], kb[0], kb[1]);
                mma16816(s[j + 1], qa[kk], kb[2], kb[3]);
            }
        }

        float rmA = -1e30f, rmB = -1e30f;
        #pragma unroll
        for (int j = 0; j < 8; ++j) {
            rmA = fmaxf(rmA, fmaxf(s[j][0], s[j][1]));
            rmB = fmaxf(rmB, fmaxf(s[j][2], s[j][3]));
        }
        rmA = fmaxf(rmA, __shfl_xor_sync(0xffffffffu, rmA, 1));
        rmA = fmaxf(rmA, __shfl_xor_sync(0xffffffffu, rmA, 2));
        rmB = fmaxf(rmB, __shfl_xor_sync(0xffffffffu, rmB, 1));
        rmB = fmaxf(rmB, __shfl_xor_sync(0xffffffffu, rmB, 2));
        float mnA = fmaxf(mA, rmA), mnB = fmaxf(mB, rmB);
        float corrA = __expf(mA - mnA), corrB = __expf(mB - mnB);
        mA = mnA; mB = mnB;

        float rsA = 0.f, rsB = 0.f;
        #pragma unroll
        for (int j = 0; j < 8; ++j) {
            s[j][0] = __expf(s[j][0] - mA);
            s[j][1] = __expf(s[j][1] - mA);
            s[j][2] = __expf(s[j][2] - mB);
            s[j][3] = __expf(s[j][3] - mB);
            rsA += s[j][0] + s[j][1];
            rsB += s[j][2] + s[j][3];
        }
        rsA += __shfl_xor_sync(0xffffffffu, rsA, 1);
        rsA += __shfl_xor_sync(0xffffffffu, rsA, 2);
        rsB += __shfl_xor_sync(0xffffffffu, rsB, 1);
        rsB += __shfl_xor_sync(0xffffffffu, rsB, 2);
        lA = lA * corrA + rsA;
        lB = lB * corrB + rsB;
        #pragma unroll
        for (int j = 0; j < 8; ++j) {
            o[j][0] *= corrA; o[j][1] *= corrA;
            o[j][2] *= corrB; o[j][3] *= corrB;
        }

        uint32_t pa[4][4];
        #pragma unroll
        for (int kk = 0; kk < 4; ++kk) {
            pa[kk][0] = packbf(s[2 * kk][0],     s[2 * kk][1]);
            pa[kk][1] = packbf(s[2 * kk][2],     s[2 * kk][3]);
            pa[kk][2] = packbf(s[2 * kk + 1][0], s[2 * kk + 1][1]);
            pa[kk][3] = packbf(s[2 * kk + 1][2], s[2 * kk + 1][3]);
        }
        #pragma unroll
        for (int kk = 0; kk < 4; ++kk) {
            #pragma unroll
            for (int d8 = 0; d8 < 8; d8 += 2) {
                uint32_t vb[4];
                ldm4t(vb, (uint32_t)__cvta_generic_to_shared(
                    &Vs[(16 * kk + vrow) * AST + d8 * 8 + vcb]));
                mma16816(o[d8],     pa[kk], vb[0], vb[1]);
                mma16816(o[d8 + 1], pa[kk], vb[2], vb[3]);
            }
        }
    }

    float iA = 1.0f / lA, iB = 1.0f / lB;
    int rowA = lane >> 2;
    int qA = q0 + warp * 16 + rowA;
    int cA = hq + (lane & 3) * 2;
    __nv_bfloat16* outA = ctxs + ((size_t)(b * SEQ) + qA) * EMBED;
    __nv_bfloat16* outB = outA + (size_t)8 * EMBED;
    #pragma unroll
    for (int j = 0; j < 8; ++j) {
        *(uint32_t*)&outA[cA + j * 8] = packbf(o[j][0] * iA, o[j][1] * iA);
        *(uint32_t*)&outB[cA + j * 8] = packbf(o[j][2] * iB, o[j][3] * iB);
    }
}

// ---------------------------------------------------------------------------
// Launch
// ---------------------------------------------------------------------------
extern "C" void kernel_launch(void* const* d_in, const int* in_sizes, int n_in,
                              void* d_out, int out_size)
{
    const float* x      = (const float*)d_in[0];
    const float* ln1_g  = (const float*)d_in[1];
    const float* ln1_b  = (const float*)d_in[2];
    const float* qkv_w  = (const float*)d_in[3];
    const float* qkv_b  = (const float*)d_in[4];
    const float* proj_w = (const float*)d_in[5];
    const float* proj_b = (const float*)d_in[6];
    const float* ln2_g  = (const float*)d_in[7];
    const float* ln2_b  = (const float*)d_in[8];
    const float* fc1_w  = (const float*)d_in[9];
    const float* fc1_b  = (const float*)d_in[10];
    const float* fc2_w  = (const float*)d_in[11];
    const float* fc2_b  = (const float*)d_in[12];
    float* out = (float*)d_out;

    float *p_qkv, *p_x1;
    __nv_bfloat16 *p_as, *p_ctxs, *p_f1s, *p_wq, *p_wp, *p_w1, *p_w2;
    cudaGetSymbolAddress((void**)&p_qkv,  g_qkv);
    cudaGetSymbolAddress((void**)&p_x1,   g_x1);
    cudaGetSymbolAddress((void**)&p_as,   g_as);
    cudaGetSymbolAddress((void**)&p_ctxs, g_ctxs);
    cudaGetSymbolAddress((void**)&p_f1s,  g_f1s);
    cudaGetSymbolAddress((void**)&p_wq,   g_wq);
    cudaGetSymbolAddress((void**)&p_wp,   g_wp);
    cudaGetSymbolAddress((void**)&p_w1,   g_w1);
    cudaGetSymbolAddress((void**)&p_w2,   g_w2);

    cudaFuncSetAttribute(tc_gemm<0>, cudaFuncAttributeMaxDynamicSharedMemorySize, GEMM_SMEM);
    cudaFuncSetAttribute(tc_gemm<1>, cudaFuncAttributeMaxDynamicSharedMemorySize, GEMM_SMEM);
    cudaFuncSetAttribute(tc_gemm<2>, cudaFuncAttributeMaxDynamicSharedMemorySize, GEMM_SMEM);

    // weight conversions, one launch
    wconv_all<<<1024, 256>>>(qkv_w, proj_w, fc1_w, fc2_w, p_wq, p_wp, p_w1, p_w2);

    // 1) LN1 -> bf16
    ln_kernel<<<MTOK, 256>>>(x, ln1_g, ln1_b, p_as);
    // 2) QKV GEMM -> fp32
    tc_gemm<0><<<dim3(QKVC / 128, MTOK / 128), 256, GEMM_SMEM>>>(
        p_as, p_wq, qkv_b, nullptr, p_qkv, nullptr, QKVC, EMBED);
    // 3) flash attention -> bf16 ctx
    attn_kernel<<<dim3(SEQ / 64, BATCH * HEADS), 128>>>(p_qkv, p_ctxs);
    // 4) proj GEMM + residual -> fp32 x1
    tc_gemm<1><<<dim3(EMBED / 128, MTOK / 128), 256, GEMM_SMEM>>>(
        p_ctxs, p_wp, proj_b, x, p_x1, nullptr, EMBED, EMBED);
    // 5) LN2 -> bf16
    ln_kernel<<<MTOK, 256>>>(p_x1, ln2_g, ln2_b, p_as);
    // 6) FC1 GEMM + GELU -> bf16
    tc_gemm<2><<<dim3(HIDDEN / 128, MTOK / 128), 256, GEMM_SMEM>>>(
        p_as, p_w1, fc1_b, nullptr, nullptr, p_f1s, HIDDEN, EMBED);
    // 7) FC2 GEMM + residual -> final fp32 output
    tc_gemm<1><<<dim3(EMBED / 128, MTOK / 128), 256, GEMM_SMEM>>>(
        p_f1s, p_w2, fc2_b, p_x1, out, nullptr, EMBED, HIDDEN);
}

// round 14
// speedup vs baseline: 5.1191x; 1.0343x over previous
#include <cuda_runtime.h>
#include <cuda_bf16.h>
#include <math.h>
#include <stdint.h>

// ---------------------------------------------------------------------------
// Problem constants
// ---------------------------------------------------------------------------
#define BATCH   8
#define SEQ     1024
#define EMBED   768
#define HEADS   12
#define HD      64
#define HIDDEN  3072
#define MTOK    (BATCH * SEQ)          // 8192 tokens
#define QKVC    (3 * EMBED)            // 2304

// ---------------------------------------------------------------------------
// Scratch (static __device__: allocation-free per harness rules)
// ---------------------------------------------------------------------------
__device__ __align__(16) float         g_qkv [(size_t)MTOK * QKVC];
__device__ __align__(16) float         g_x1  [(size_t)MTOK * EMBED];
__device__ __align__(16) __nv_bfloat16 g_as  [(size_t)MTOK * EMBED];
__device__ __align__(16) __nv_bfloat16 g_ctxs[(size_t)MTOK * EMBED];
__device__ __align__(16) __nv_bfloat16 g_f1s [(size_t)MTOK * HIDDEN];
__device__ __align__(16) __nv_bfloat16 g_wq  [(size_t)QKVC  * EMBED];
__device__ __align__(16) __nv_bfloat16 g_wp  [(size_t)EMBED * EMBED];
__device__ __align__(16) __nv_bfloat16 g_w1  [(size_t)HIDDEN* EMBED];
__device__ __align__(16) __nv_bfloat16 g_w2  [(size_t)EMBED * HIDDEN];

// ---------------------------------------------------------------------------
// Shared PTX helpers
// ---------------------------------------------------------------------------
__device__ __forceinline__ void ldm4(uint32_t* r, uint32_t addr) {
    asm volatile("ldmatrix.sync.aligned.m8n8.x4.shared.b16 {%0,%1,%2,%3}, [%4];"
        : "=r"(r[0]), "=r"(r[1]), "=r"(r[2]), "=r"(r[3]) : "r"(addr));
}
__device__ __forceinline__ void ldm4t(uint32_t* r, uint32_t addr) {
    asm volatile("ldmatrix.sync.aligned.m8n8.x4.trans.shared.b16 {%0,%1,%2,%3}, [%4];"
        : "=r"(r[0]), "=r"(r[1]), "=r"(r[2]), "=r"(r[3]) : "r"(addr));
}
__device__ __forceinline__ void mma16816(float* c, const uint32_t* a, uint32_t b0, uint32_t b1) {
    asm volatile("mma.sync.aligned.m16n8k16.row.col.f32.bf16.bf16.f32 "
        "{%0,%1,%2,%3}, {%4,%5,%6,%7}, {%8,%9}, {%0,%1,%2,%3};"
        : "+f"(c[0]), "+f"(c[1]), "+f"(c[2]), "+f"(c[3])
        : "r"(a[0]), "r"(a[1]), "r"(a[2]), "r"(a[3]), "r"(b0), "r"(b1));
}
__device__ __forceinline__ uint32_t packbf(float lo, float hi) {
    __nv_bfloat162 t = __floats2bfloat162_rn(lo, hi);
    return *(uint32_t*)&t;
}
__device__ __forceinline__ void cpasync16(uint32_t dst, const void* src) {
    asm volatile("cp.async.cg.shared.global [%0], [%1], 16;" :: "r"(dst), "l"(src));
}
__device__ __forceinline__ void cp_commit() { asm volatile("cp.async.commit_group;"); }
template<int N> __device__ __forceinline__ void cp_wait() {
    asm volatile("cp.async.wait_group %0;" :: "n"(N));
}

// ---------------------------------------------------------------------------
// Fused weight convert: all four weight tensors fp32 -> bf16 in one launch
// ---------------------------------------------------------------------------
#define WQ_N ((size_t)QKVC  * EMBED)
#define WP_N ((size_t)EMBED * EMBED)
#define W1_N ((size_t)HIDDEN * EMBED)
#define W2_N ((size_t)EMBED * HIDDEN)

__global__ void wconv_all(const float* __restrict__ wq, const float* __restrict__ wp,
                          const float* __restrict__ w1, const float* __restrict__ w2,
                          __nv_bfloat16* __restrict__ oq, __nv_bfloat16* __restrict__ op,
                          __nv_bfloat16* __restrict__ o1, __nv_bfloat16* __restrict__ o2)
{
    const size_t total = WQ_N + WP_N + W1_N + W2_N;
    size_t i = ((size_t)blockIdx.x * blockDim.x + threadIdx.x) * 4;
    size_t stride = (size_t)gridDim.x * blockDim.x * 4;
    for (; i < total; i += stride) {
        const float* src; __nv_bfloat16* dst; size_t off = i;
        if (off < WQ_N)                         { src = wq; dst = oq; }
        else if ((off -= WQ_N) < WP_N)          { src = wp; dst = op; }
        else if ((off -= WP_N) < W1_N)          { src = w1; dst = o1; }
        else { off -= W1_N;                       src = w2; dst = o2; }
        float4 v = *(const float4*)&src[off];
        __nv_bfloat162 p0, p1;
        p0.x = __float2bfloat16(v.x); p0.y = __float2bfloat16(v.y);
        p1.x = __float2bfloat16(v.z); p1.y = __float2bfloat16(v.w);
        *(__nv_bfloat162*)&dst[off]     = p0;
        *(__nv_bfloat162*)&dst[off + 2] = p1;
    }
}

// ---------------------------------------------------------------------------
// LayerNorm -> bf16 row (768)
// ---------------------------------------------------------------------------
__global__ __launch_bounds__(256) void ln_kernel(
    const float* __restrict__ x, const float* __restrict__ g,
    const float* __restrict__ bvec, __nv_bfloat16* __restrict__ out)
{
    int row = blockIdx.x;
    const float* xr = x + (size_t)row * EMBED;
    int t = threadIdx.x;

    float v0 = xr[t], v1 = xr[t + 256], v2 = xr[t + 512];
    float s  = v0 + v1 + v2;
    float ss = v0 * v0 + v1 * v1 + v2 * v2;

    __shared__ float red0[8], red1[8];
    int lane = t & 31, wid = t >> 5;
    #pragma unroll
    for (int o = 16; o; o >>= 1) {
        s  += __shfl_xor_sync(0xffffffffu, s,  o);
        ss += __shfl_xor_sync(0xffffffffu, ss, o);
    }
    if (lane == 0) { red0[wid] = s; red1[wid] = ss; }
    __syncthreads();
    if (t < 32) {
        s  = (t < 8) ? red0[t] : 0.f;
        ss = (t < 8) ? red1[t] : 0.f;
        #pragma unroll
        for (int o = 4; o; o >>= 1) {
            s  += __shfl_xor_sync(0xffffffffu, s,  o);
            ss += __shfl_xor_sync(0xffffffffu, ss, o);
        }
        if (t == 0) { red0[0] = s; red1[0] = ss; }
    }
    __syncthreads();
    float mean = red0[0] * (1.0f / EMBED);
    float var  = red1[0] * (1.0f / EMBED) - mean * mean;
    float rstd = rsqrtf(var + 1e-5f);

    __nv_bfloat16* orow = out + (size_t)row * EMBED;
    orow[t]       = __float2bfloat16((v0 - mean) * rstd * g[t]       + bvec[t]);
    orow[t + 256] = __float2bfloat16((v1 - mean) * rstd * g[t + 256] + bvec[t + 256]);
    orow[t + 512] = __float2bfloat16((v2 - mean) * rstd * g[t + 512] + bvec[t + 512]);
}

// ---------------------------------------------------------------------------
// bf16 GEMM, raw mma.m16n8k16, warp tile 64x64, 4 warps, 128x128 CTA tile.
// 3-stage cp.async pipeline. Direct register epilogue (no smem staging).
// EPI: 0 = bias -> fp32 C; 1 = bias+Res -> fp32 C; 2 = bias+GELU -> bf16 Cs
// ---------------------------------------------------------------------------
#define LDS 40
#define STAGES 3
#define STAGE_ELEMS (128 * LDS)
#define GEMM_SMEM (STAGES * 2 * STAGE_ELEMS * 2)   // 61440 B

template<int EPI>
__global__ __launch_bounds__(128, 2) void tc_gemm(
    const __nv_bfloat16* __restrict__ A, const __nv_bfloat16* __restrict__ B,
    const float* __restrict__ bias, const float* __restrict__ Res,
    float* __restrict__ C, __nv_bfloat16* __restrict__ Cs,
    int N, int Kp)
{
    extern __shared__ __align__(16) char dynsmem[];
    __nv_bfloat16* Asm = (__nv_bfloat16*)dynsmem;
    __nv_bfloat16* Bsm = Asm + STAGES * STAGE_ELEMS;
    uint32_t sAu = (uint32_t)__cvta_generic_to_shared(Asm);
    uint32_t sBu = (uint32_t)__cvta_generic_to_shared(Bsm);

    int tid  = threadIdx.x;
    int warp = tid >> 5, lane = tid & 31;
    int wm = warp >> 1, wn = warp & 1;      // 2x2 warps, each 64x64
    int bm = blockIdx.y * 128, bn = blockIdx.x * 128;

    // cp.async: thread t owns row t of both A and B chunks (4 x 16B each)
    const __nv_bfloat16* Agp = A + (size_t)(bm + tid) * Kp;
    const __nv_bfloat16* Bgp = B + (size_t)(bn + tid) * Kp;
    uint32_t dstA = sAu + (uint32_t)(tid * LDS) * 2;
    uint32_t dstB = sBu + (uint32_t)(tid * LDS) * 2;

    auto load_chunk = [&](int chunk, int st) {
        uint32_t so = (uint32_t)st * STAGE_ELEMS * 2;
        const __nv_bfloat16* a = Agp + (chunk << 5);
        const __nv_bfloat16* b = Bgp + (chunk << 5);
        #pragma unroll
        for (int seg = 0; seg < 4; ++seg) {
            cpasync16(dstA + so + seg * 16, a + seg * 8);
            cpasync16(dstB + so + seg * 16, b + seg * 8);
        }
    };

    float acc[4][8][4];
    #pragma unroll
    for (int mi = 0; mi < 4; ++mi)
        #pragma unroll
        for (int nj = 0; nj < 8; ++nj)
            #pragma unroll
            for (int c = 0; c < 4; ++c) acc[mi][nj][c] = 0.f;

    int nk = Kp >> 5;
    int krow = ((lane >> 4) << 3) + (lane & 7);
    int kcb  = (lane & 8);
    int arow = lane & 15;
    int acb  = (lane >> 4) << 3;

    #pragma unroll
    for (int s = 0; s < STAGES - 1; ++s) {
        load_chunk(s, s);
        cp_commit();
    }

    for (int t = 0; t < nk; ++t) {
        cp_wait<STAGES - 2>();
        __syncthreads();

        int nxt = t + STAGES - 1;
        if (nxt < nk) load_chunk(nxt, nxt % STAGES);
        cp_commit();

        int st = t % STAGES;
        uint32_t aBase = sAu + (uint32_t)(st * STAGE_ELEMS) * 2;
        uint32_t bBase = sBu + (uint32_t)(st * STAGE_ELEMS) * 2;
        #pragma unroll
        for (int ks = 0; ks < 2; ++ks) {
            uint32_t af[4][4];
            #pragma unroll
            for (int mi = 0; mi < 4; ++mi)
                ldm4(af[mi], aBase + (uint32_t)((wm * 64 + mi * 16 + arow) * LDS + ks * 16 + acb) * 2);
            #pragma unroll
            for (int nb = 0; nb < 4; ++nb) {
                uint32_t kb[4];
                ldm4(kb, bBase + (uint32_t)((wn * 64 + nb * 16 + krow) * LDS + ks * 16 + kcb) * 2);
                #pragma unroll
                for (int mi = 0; mi < 4; ++mi) {
                    mma16816(acc[mi][2 * nb],     af[mi], kb[0], kb[1]);
                    mma16816(acc[mi][2 * nb + 1], af[mi], kb[2], kb[3]);
                }
            }
        }
    }

    // ---- direct register epilogue ----
    int r  = lane >> 2;
    int cc = (lane & 3) << 1;
    #pragma unroll
    for (int mi = 0; mi < 4; ++mi) {
        int row0 = bm + wm * 64 + mi * 16 + r;
        #pragma unroll
        for (int nj = 0; nj < 8; ++nj) {
            int col = bn + wn * 64 + nj * 8 + cc;
            float2 bb = *(const float2*)&bias[col];
            float v0 = acc[mi][nj][0] + bb.x;
            float v1 = acc[mi][nj][1] + bb.y;
            float v2 = acc[mi][nj][2] + bb.x;
            float v3 = acc[mi][nj][3] + bb.y;
            size_t off0 = (size_t)row0 * N + col;
            size_t off1 = off0 + (size_t)8 * N;
            if (EPI == 2) {
                v0 = 0.5f * v0 * (1.0f + erff(v0 * 0.70710678118654752f));
                v1 = 0.5f * v1 * (1.0f + erff(v1 * 0.70710678118654752f));
                v2 = 0.5f * v2 * (1.0f + erff(v2 * 0.70710678118654752f));
                v3 = 0.5f * v3 * (1.0f + erff(v3 * 0.70710678118654752f));
                *(uint32_t*)&Cs[off0] = packbf(v0, v1);
                *(uint32_t*)&Cs[off1] = packbf(v2, v3);
            } else {
                if (EPI == 1) {
                    float2 r0 = *(const float2*)&Res[off0];
                    float2 r1 = *(const float2*)&Res[off1];
                    v0 += r0.x; v1 += r0.y; v2 += r1.x; v3 += r1.y;
                }
                *(float2*)&C[off0] = make_float2(v0, v1);
                *(float2*)&C[off1] = make_float2(v2, v3);
            }
        }
    }
}

// ---------------------------------------------------------------------------
// FlashAttention-2 style fused attention (validated R10), mma.m16n8k16 bf16.
// ---------------------------------------------------------------------------
#define AST 72

__global__ __launch_bounds__(128) void attn_kernel(
    const float* __restrict__ qkv, __nv_bfloat16* __restrict__ ctxs)
{
    __shared__ __align__(16) __nv_bfloat16 Qs[64 * AST];
    __shared__ __align__(16) __nv_bfloat16 Ks[64 * AST];
    __shared__ __align__(16) __nv_bfloat16 Vs[64 * AST];

    int bh = blockIdx.y;
    int b  = bh / HEADS;
    int h  = bh % HEADS;
    int q0 = blockIdx.x * 64;
    int tid = threadIdx.x, warp = tid >> 5, lane = tid & 31;
    int hq = h * HD;
    const float* base = qkv + (size_t)(b * SEQ) * QKVC;

    for (int i = tid; i < 1024; i += 128) {
        int r = i >> 4, c4 = (i & 15) << 2;
        float4 v = *(const float4*)(base + (size_t)(q0 + r) * QKVC + hq + c4);
        *(__nv_bfloat162*)&Qs[r * AST + c4]     = __floats2bfloat162_rn(v.x * 0.125f, v.y * 0.125f);
        *(__nv_bfloat162*)&Qs[r * AST + c4 + 2] = __floats2bfloat162_rn(v.z * 0.125f, v.w * 0.125f);
    }
    __syncthreads();

    uint32_t qa[4][4];
    {
        int qr = warp * 16 + (lane & 15);
        int cb = (lane >> 4) << 3;
        #pragma unroll
        for (int kk = 0; kk < 4; ++kk)
            ldm4(qa[kk], (uint32_t)__cvta_generic_to_shared(&Qs[qr * AST + kk * 16 + cb]));
    }

    float o[8][4];
    #pragma unroll
    for (int j = 0; j < 8; ++j)
        #pragma unroll
        for (int c = 0; c < 4; ++c) o[j][c] = 0.f;
    float mA = -1e30f, mB = -1e30f, lA = 0.f, lB = 0.f;

    int krow = ((lane >> 4) << 3) + (lane & 7);
    int kcb  = (lane & 8);
    int vrow = (lane & 15);
    int vcb  = (lane >> 4) << 3;

    for (int t = 0; t < 16; ++t) {
        __syncthreads();
        for (int i = tid; i < 1024; i += 128) {
            int r = i >> 4, c4 = (i & 15) << 2;
            const float* trow = base + (size_t)(t * 64 + r) * QKVC + hq;
            float4 kv = *(const float4*)(trow + EMBED + c4);
            float4 vv = *(const float4*)(trow + 2 * EMBED + c4);
            *(__nv_bfloat162*)&Ks[r * AST + c4]     = __floats2bfloat162_rn(kv.x, kv.y);
            *(__nv_bfloat162*)&Ks[r * AST + c4 + 2] = __floats2bfloat162_rn(kv.z, kv.w);
            *(__nv_bfloat162*)&Vs[r * AST + c4]     = __floats2bfloat162_rn(vv.x, vv.y);
            *(__nv_bfloat162*)&Vs[r * AST + c4 + 2] = __floats2bfloat162_rn(vv.z, vv.w);
        }
        __syncthreads();

        float s[8][4];
        #pragma unroll
        for (int j = 0; j < 8; ++j)
            #pragma unroll
            for (int c = 0; c < 4; ++c) s[j][c] = 0.f;
        #pragma unroll
        for (int kk = 0; kk < 4; ++kk) {
            #pragma unroll
            for (int j = 0; j < 8; j += 2) {
                uint32_t kb[4];
                ldm4(kb, (uint32_t)__cvta_generic_to_shared(
                    &Ks[(j * 8 + krow) * AST + kk * 16 + kcb]));
                mma16816(s[j],     qa[kk], kb[0], kb[1]);
                mma16816(s[j + 1], qa[kk], kb[2], kb[3]);
            }
        }

        float rmA = -1e30f, rmB = -1e30f;
        #pragma unroll
        for (int j = 0; j < 8; ++j) {
            rmA = fmaxf(rmA, fmaxf(s[j][0], s[j][1]));
            rmB = fmaxf(rmB, fmaxf(s[j][2], s[j][3]));
        }
        rmA = fmaxf(rmA, __shfl_xor_sync(0xffffffffu, rmA, 1));
        rmA = fmaxf(rmA, __shfl_xor_sync(0xffffffffu, rmA, 2));
        rmB = fmaxf(rmB, __shfl_xor_sync(0xffffffffu, rmB, 1));
        rmB = fmaxf(rmB, __shfl_xor_sync(0xffffffffu, rmB, 2));
        float mnA = fmaxf(mA, rmA), mnB = fmaxf(mB, rmB);
        float corrA = __expf(mA - mnA), corrB = __expf(mB - mnB);
        mA = mnA; mB = mnB;

        float rsA = 0.f, rsB = 0.f;
        #pragma unroll
        for (int j = 0; j < 8; ++j) {
            s[j][0] = __expf(s[j][0] - mA);
            s[j][1] = __expf(s[j][1] - mA);
            s[j][2] = __expf(s[j][2] - mB);
            s[j][3] = __expf(s[j][3] - mB);
            rsA += s[j][0] + s[j][1];
            rsB += s[j][2] + s[j][3];
        }
        rsA += __shfl_xor_sync(0xffffffffu, rsA, 1);
        rsA += __shfl_xor_sync(0xffffffffu, rsA, 2);
        rsB += __shfl_xor_sync(0xffffffffu, rsB, 1);
        rsB += __shfl_xor_sync(0xffffffffu, rsB, 2);
        lA = lA * corrA + rsA;
        lB = lB * corrB + rsB;
        #pragma unroll
        for (int j = 0; j < 8; ++j) {
            o[j][0] *= corrA; o[j][1] *= corrA;
            o[j][2] *= corrB; o[j][3] *= corrB;
        }

        uint32_t pa[4][4];
        #pragma unroll
        for (int kk = 0; kk < 4; ++kk) {
            pa[kk][0] = packbf(s[2 * kk][0],     s[2 * kk][1]);
            pa[kk][1] = packbf(s[2 * kk][2],     s[2 * kk][3]);
            pa[kk][2] = packbf(s[2 * kk + 1][0], s[2 * kk + 1][1]);
            pa[kk][3] = packbf(s[2 * kk + 1][2], s[2 * kk + 1][3]);
        }
        #pragma unroll
        for (int kk = 0; kk < 4; ++kk) {
            #pragma unroll
            for (int d8 = 0; d8 < 8; d8 += 2) {
                uint32_t vb[4];
                ldm4t(vb, (uint32_t)__cvta_generic_to_shared(
                    &Vs[(16 * kk + vrow) * AST + d8 * 8 + vcb]));
                mma16816(o[d8],     pa[kk], vb[0], vb[1]);
                mma16816(o[d8 + 1], pa[kk], vb[2], vb[3]);
            }
        }
    }

    float iA = 1.0f / lA, iB = 1.0f / lB;
    int rowA = lane >> 2;
    int qA = q0 + warp * 16 + rowA;
    int cA = hq + (lane & 3) * 2;
    __nv_bfloat16* outA = ctxs + ((size_t)(b * SEQ) + qA) * EMBED;
    __nv_bfloat16* outB = outA + (size_t)8 * EMBED;
    #pragma unroll
    for (int j = 0; j < 8; ++j) {
        *(uint32_t*)&outA[cA + j * 8] = packbf(o[j][0] * iA, o[j][1] * iA);
        *(uint32_t*)&outB[cA + j * 8] = packbf(o[j][2] * iB, o[j][3] * iB);
    }
}

// ---------------------------------------------------------------------------
// Launch
// ---------------------------------------------------------------------------
extern "C" void kernel_launch(void* const* d_in, const int* in_sizes, int n_in,
                              void* d_out, int out_size)
{
    const float* x      = (const float*)d_in[0];
    const float* ln1_g  = (const float*)d_in[1];
    const float* ln1_b  = (const float*)d_in[2];
    const float* qkv_w  = (const float*)d_in[3];
    const float* qkv_b  = (const float*)d_in[4];
    const float* proj_w = (const float*)d_in[5];
    const float* proj_b = (const float*)d_in[6];
    const float* ln2_g  = (const float*)d_in[7];
    const float* ln2_b  = (const float*)d_in[8];
    const float* fc1_w  = (const float*)d_in[9];
    const float* fc1_b  = (const float*)d_in[10];
    const float* fc2_w  = (const float*)d_in[11];
    const float* fc2_b  = (const float*)d_in[12];
    float* out = (float*)d_out;

    float *p_qkv, *p_x1;
    __nv_bfloat16 *p_as, *p_ctxs, *p_f1s, *p_wq, *p_wp, *p_w1, *p_w2;
    cudaGetSymbolAddress((void**)&p_qkv,  g_qkv);
    cudaGetSymbolAddress((void**)&p_x1,   g_x1);
    cudaGetSymbolAddress((void**)&p_as,   g_as);
    cudaGetSymbolAddress((void**)&p_ctxs, g_ctxs);
    cudaGetSymbolAddress((void**)&p_f1s,  g_f1s);
    cudaGetSymbolAddress((void**)&p_wq,   g_wq);
    cudaGetSymbolAddress((void**)&p_wp,   g_wp);
    cudaGetSymbolAddress((void**)&p_w1,   g_w1);
    cudaGetSymbolAddress((void**)&p_w2,   g_w2);

    cudaFuncSetAttribute(tc_gemm<0>, cudaFuncAttributeMaxDynamicSharedMemorySize, GEMM_SMEM);
    cudaFuncSetAttribute(tc_gemm<1>, cudaFuncAttributeMaxDynamicSharedMemorySize, GEMM_SMEM);
    cudaFuncSetAttribute(tc_gemm<2>, cudaFuncAttributeMaxDynamicSharedMemorySize, GEMM_SMEM);

    wconv_all<<<1024, 256>>>(qkv_w, proj_w, fc1_w, fc2_w, p_wq, p_wp, p_w1, p_w2);

    // 1) LN1 -> bf16
    ln_kernel<<<MTOK, 256>>>(x, ln1_g, ln1_b, p_as);
    // 2) QKV GEMM -> fp32
    tc_gemm<0><<<dim3(QKVC / 128, MTOK / 128), 128, GEMM_SMEM>>>(
        p_as, p_wq, qkv_b, nullptr, p_qkv, nullptr, QKVC, EMBED);
    // 3) flash attention -> bf16 ctx
    attn_kernel<<<dim3(SEQ / 64, BATCH * HEADS), 128>>>(p_qkv, p_ctxs);
    // 4) proj GEMM + residual -> fp32 x1
    tc_gemm<1><<<dim3(EMBED / 128, MTOK / 128), 128, GEMM_SMEM>>>(
        p_ctxs, p_wp, proj_b, x, p_x1, nullptr, EMBED, EMBED);
    // 5) LN2 -> bf16
    ln_kernel<<<MTOK, 256>>>(p_x1, ln2_g, ln2_b, p_as);
    // 6) FC1 GEMM + GELU -> bf16
    tc_gemm<2><<<dim3(HIDDEN / 128, MTOK / 128), 128, GEMM_SMEM>>>(
        p_as, p_w1, fc1_b, nullptr, nullptr, p_f1s, HIDDEN, EMBED);
    // 7) FC2 GEMM + residual -> final fp32 output
    tc_gemm<1><<<dim3(EMBED / 128, MTOK / 128), 128, GEMM_SMEM>>>(
        p_f1s, p_w2, fc2_b, p_x1, out, nullptr, EMBED, HIDDEN);
}